// round 1
// baseline (speedup 1.0000x reference)
#include <cuda_runtime.h>
#include <math.h>

#define BB  4
#define SS  1024
#define DD  1024
#define HH  16
#define DHH 64

// ---- persistent scratch (no allocations allowed) ----
__device__ float g_q[BB*HH*SS*DHH];     // [bh][s][e]
__device__ float g_k[BB*HH*SS*DHH];
__device__ float g_v[BB*HH*SS*DHH];
__device__ float g_z[BB*HH*SS*DHH];     // per-head attention output
__device__ float g_sum[BB*SS*DHH];      // head-summed [t][e]

// ============================================================
// QKV projection: out[(b*H+h)*S+s][e] = sum_d x[b,s,d]*W[h,d,e] + bias[h,e]
// M=4096, N=1024 (h*64+e), K=1024. BM=128 BN=64 BK=16, 256 thr, 8x4/thread.
// blockIdx.z selects Q / K / V.
// ============================================================
__global__ __launch_bounds__(256) void qkv_gemm_kernel(
    const float* __restrict__ x,
    const float* __restrict__ Wq, const float* __restrict__ bq,
    const float* __restrict__ Wk, const float* __restrict__ bk,
    const float* __restrict__ Wv, const float* __restrict__ bv)
{
    __shared__ float sA[16][132];   // sA[k][m], m in [0,128)
    __shared__ float sB[16][68];    // sB[k][n], n in [0,64)

    const float* W; const float* bias; float* out;
    if (blockIdx.z == 0)      { W = Wq; bias = bq; out = g_q; }
    else if (blockIdx.z == 1) { W = Wk; bias = bk; out = g_k; }
    else                      { W = Wv; bias = bv; out = g_v; }

    const int m0 = blockIdx.y * 128;
    const int n0 = blockIdx.x * 64;
    const int h  = n0 >> 6;
    const float* Wh = W + (size_t)h * DD * DHH;   // [D][64] contiguous

    const int tid = threadIdx.x;
    const int tx = tid & 15;     // 0..15 -> 4 cols
    const int ty = tid >> 4;     // 0..15 -> 8 rows

    float acc[8][4];
    #pragma unroll
    for (int i = 0; i < 8; i++)
        #pragma unroll
        for (int j = 0; j < 4; j++) acc[i][j] = 0.f;

    const int ar = tid >> 2;          // 0..63
    const int ac = (tid & 3) * 4;     // 0,4,8,12
    const int br = tid >> 4;          // 0..15
    const int bc = (tid & 15) * 4;    // 0..60

    for (int k0 = 0; k0 < DD; k0 += 16) {
        float4 a0 = *(const float4*)&x[(size_t)(m0 + ar)      * DD + k0 + ac];
        float4 a1 = *(const float4*)&x[(size_t)(m0 + ar + 64) * DD + k0 + ac];
        float4 b4 = *(const float4*)&Wh[(size_t)(k0 + br) * DHH + bc];
        __syncthreads();
        sA[ac + 0][ar] = a0.x;  sA[ac + 1][ar] = a0.y;
        sA[ac + 2][ar] = a0.z;  sA[ac + 3][ar] = a0.w;
        sA[ac + 0][ar + 64] = a1.x;  sA[ac + 1][ar + 64] = a1.y;
        sA[ac + 2][ar + 64] = a1.z;  sA[ac + 3][ar + 64] = a1.w;
        *(float4*)&sB[br][bc] = b4;
        __syncthreads();
        #pragma unroll
        for (int k = 0; k < 16; k++) {
            float a[8], bb[4];
            *(float4*)&a[0] = *(const float4*)&sA[k][ty * 8];
            *(float4*)&a[4] = *(const float4*)&sA[k][ty * 8 + 4];
            *(float4*)&bb[0] = *(const float4*)&sB[k][tx * 4];
            #pragma unroll
            for (int i = 0; i < 8; i++)
                #pragma unroll
                for (int j = 0; j < 4; j++)
                    acc[i][j] += a[i] * bb[j];
        }
    }

    float4 bias4 = *(const float4*)&bias[n0 + tx * 4];
    #pragma unroll
    for (int i = 0; i < 8; i++) {
        int m = m0 + ty * 8 + i;
        int b = m >> 10;
        int s = m & 1023;
        float4 r;
        r.x = acc[i][0] + bias4.x;
        r.y = acc[i][1] + bias4.y;
        r.z = acc[i][2] + bias4.z;
        r.w = acc[i][3] + bias4.w;
        *(float4*)&out[((size_t)(b * HH + h) * SS + s) * DHH + tx * 4] = r;
    }
}

// ============================================================
// Flash attention, causal, per (q-tile of 64, head). 256 threads.
// smem: Qt[e][m], Kt[e][n] (reused as Pt[k][m]), Vs[k][e]. 48KB total.
// ============================================================
__global__ __launch_bounds__(256) void attn_kernel()
{
    __shared__ float Qt[64][64];
    __shared__ float Kt[64][64];   // K transposed; later reused as P transposed
    __shared__ float Vs[64][64];

    const int qt = blockIdx.x;     // 0..15
    const int bh = blockIdx.y;     // 0..63
    const int q0 = qt * 64;
    const int tid = threadIdx.x;
    const int tx = tid & 15;
    const int ty = tid >> 4;

    const float* Qg = g_q + ((size_t)bh * SS + q0) * DHH;
    const float* Kg = g_k + (size_t)bh * SS * DHH;
    const float* Vg = g_v + (size_t)bh * SS * DHH;

    // Q -> Qt transposed
    {
        const int lr = tid >> 4;          // 0..15
        const int lc = (tid & 15) * 4;    // 0..60
        #pragma unroll
        for (int c = 0; c < 4; c++) {
            int row = lr + c * 16;
            float4 v = *(const float4*)&Qg[(size_t)row * DHH + lc];
            Qt[lc + 0][row] = v.x;  Qt[lc + 1][row] = v.y;
            Qt[lc + 2][row] = v.z;  Qt[lc + 3][row] = v.w;
        }
    }

    float o[4][4];
    #pragma unroll
    for (int i = 0; i < 4; i++)
        #pragma unroll
        for (int j = 0; j < 4; j++) o[i][j] = 0.f;
    float mrow[4] = {-1e30f, -1e30f, -1e30f, -1e30f};
    float lrow[4] = {0.f, 0.f, 0.f, 0.f};

    for (int kt = 0; kt <= qt; kt++) {
        __syncthreads();   // prior iter done reading Kt/Vs (also fences Qt stores)
        {
            const int lr = tid >> 4;
            const int lc = (tid & 15) * 4;
            #pragma unroll
            for (int c = 0; c < 4; c++) {
                int row = lr + c * 16;
                float4 kk = *(const float4*)&Kg[((size_t)kt * 64 + row) * DHH + lc];
                float4 vv = *(const float4*)&Vg[((size_t)kt * 64 + row) * DHH + lc];
                Kt[lc + 0][row] = kk.x;  Kt[lc + 1][row] = kk.y;
                Kt[lc + 2][row] = kk.z;  Kt[lc + 3][row] = kk.w;
                *(float4*)&Vs[row][lc] = vv;
            }
        }
        __syncthreads();

        // S = Q K^T  (4x4 fragment per thread)
        float s[4][4];
        #pragma unroll
        for (int i = 0; i < 4; i++)
            #pragma unroll
            for (int j = 0; j < 4; j++) s[i][j] = 0.f;
        #pragma unroll 16
        for (int e = 0; e < 64; e++) {
            float4 a = *(const float4*)&Qt[e][ty * 4];
            float4 b = *(const float4*)&Kt[e][tx * 4];
            s[0][0] += a.x * b.x; s[0][1] += a.x * b.y; s[0][2] += a.x * b.z; s[0][3] += a.x * b.w;
            s[1][0] += a.y * b.x; s[1][1] += a.y * b.y; s[1][2] += a.y * b.z; s[1][3] += a.y * b.w;
            s[2][0] += a.z * b.x; s[2][1] += a.z * b.y; s[2][2] += a.z * b.z; s[2][3] += a.z * b.w;
            s[3][0] += a.w * b.x; s[3][1] += a.w * b.y; s[3][2] += a.w * b.z; s[3][3] += a.w * b.w;
        }

        // scale + causal mask + online softmax
        #pragma unroll
        for (int i = 0; i < 4; i++) {
            const int gr = q0 + ty * 4 + i;
            float mnew = mrow[i];
            #pragma unroll
            for (int j = 0; j < 4; j++) {
                float v = s[i][j] * 0.125f;                  // 1/sqrt(64)
                int gc = kt * 64 + tx * 4 + j;
                if (gc > gr) v -= 1e11f;                     // matches reference NEG mask
                s[i][j] = v;
                mnew = fmaxf(mnew, v);
            }
            #pragma unroll
            for (int d = 8; d > 0; d >>= 1)
                mnew = fmaxf(mnew, __shfl_xor_sync(0xffffffffu, mnew, d));
            float alpha = expf(mrow[i] - mnew);
            mrow[i] = mnew;
            float rs = 0.f;
            #pragma unroll
            for (int j = 0; j < 4; j++) {
                s[i][j] = expf(s[i][j] - mnew);
                rs += s[i][j];
            }
            #pragma unroll
            for (int d = 8; d > 0; d >>= 1)
                rs += __shfl_xor_sync(0xffffffffu, rs, d);
            lrow[i] = lrow[i] * alpha + rs;
            #pragma unroll
            for (int j = 0; j < 4; j++) o[i][j] *= alpha;
        }

        __syncthreads();   // everyone done reading Kt
        // P -> Kt buffer, transposed: Pt[k][m]
        #pragma unroll
        for (int i = 0; i < 4; i++)
            #pragma unroll
            for (int j = 0; j < 4; j++)
                Kt[tx * 4 + j][ty * 4 + i] = s[i][j];
        __syncthreads();

        // O += P @ V
        #pragma unroll 16
        for (int k = 0; k < 64; k++) {
            float4 p = *(const float4*)&Kt[k][ty * 4];
            float4 v = *(const float4*)&Vs[k][tx * 4];
            o[0][0] += p.x * v.x; o[0][1] += p.x * v.y; o[0][2] += p.x * v.z; o[0][3] += p.x * v.w;
            o[1][0] += p.y * v.x; o[1][1] += p.y * v.y; o[1][2] += p.y * v.z; o[1][3] += p.y * v.w;
            o[2][0] += p.z * v.x; o[2][1] += p.z * v.y; o[2][2] += p.z * v.z; o[2][3] += p.z * v.w;
            o[3][0] += p.w * v.x; o[3][1] += p.w * v.y; o[3][2] += p.w * v.z; o[3][3] += p.w * v.w;
        }
    }

    float* Zg = g_z + ((size_t)bh * SS + q0) * DHH;
    #pragma unroll
    for (int i = 0; i < 4; i++) {
        float inv = 1.f / lrow[i];
        float4 r;
        r.x = o[i][0] * inv;  r.y = o[i][1] * inv;
        r.z = o[i][2] * inv;  r.w = o[i][3] * inv;
        *(float4*)&Zg[(size_t)(ty * 4 + i) * DHH + tx * 4] = r;
    }
}

// ============================================================
// Deterministic head sum: g_sum[t][e] = sum_h g_z[(b*H+h)][s][e]
// ============================================================
__global__ __launch_bounds__(256) void headsum_kernel()
{
    int idx = blockIdx.x * blockDim.x + threadIdx.x;   // 0..262143
    int e = idx & 63;
    int s = (idx >> 6) & 1023;
    int b = idx >> 16;
    const float* zp = g_z + ((size_t)(b * HH) * SS + s) * DHH + e;
    float acc = 0.f;
    #pragma unroll
    for (int h = 0; h < HH; h++) acc += zp[(size_t)h * SS * DHH];
    g_sum[idx] = acc;
}

// ============================================================
// FF: out[t][n] = gelu(sum_e g_sum[t][e] * Wf[e][n] + bf[n]), exact erf gelu
// block: 4 tokens x 1024 cols, 256 threads (4 cols each)
// ============================================================
__device__ __forceinline__ float gelu_exact(float v)
{
    return 0.5f * v * (1.0f + erff(v * 0.70710678118654752f));
}

__global__ __launch_bounds__(256) void ff_kernel(const float* __restrict__ Wf,
                                                 const float* __restrict__ bf,
                                                 float* __restrict__ out)
{
    __shared__ float ssum[4][64];
    const int t0 = blockIdx.x * 4;
    const int tid = threadIdx.x;

    ssum[tid >> 6][tid & 63] = g_sum[(size_t)(t0 + (tid >> 6)) * DHH + (tid & 63)];
    __syncthreads();

    const int col = tid * 4;
    float acc[4][4];
    #pragma unroll
    for (int t = 0; t < 4; t++)
        #pragma unroll
        for (int j = 0; j < 4; j++) acc[t][j] = 0.f;

    #pragma unroll 8
    for (int e = 0; e < 64; e++) {
        float4 w = *(const float4*)&Wf[(size_t)e * DD + col];
        #pragma unroll
        for (int t = 0; t < 4; t++) {
            float sv = ssum[t][e];
            acc[t][0] += sv * w.x;
            acc[t][1] += sv * w.y;
            acc[t][2] += sv * w.z;
            acc[t][3] += sv * w.w;
        }
    }

    float4 b4 = *(const float4*)&bf[col];
    #pragma unroll
    for (int t = 0; t < 4; t++) {
        float4 r;
        r.x = gelu_exact(acc[t][0] + b4.x);
        r.y = gelu_exact(acc[t][1] + b4.y);
        r.z = gelu_exact(acc[t][2] + b4.z);
        r.w = gelu_exact(acc[t][3] + b4.w);
        *(float4*)&out[(size_t)(t0 + t) * DD + col] = r;
    }
}

// ============================================================
extern "C" void kernel_launch(void* const* d_in, const int* in_sizes, int n_in,
                              void* d_out, int out_size)
{
    const float* x  = (const float*)d_in[0];
    const float* Wq = (const float*)d_in[1];
    const float* bq = (const float*)d_in[2];
    const float* Wk = (const float*)d_in[3];
    const float* bk = (const float*)d_in[4];
    const float* Wv = (const float*)d_in[5];
    const float* bv = (const float*)d_in[6];
    const float* Wf = (const float*)d_in[7];
    const float* bf = (const float*)d_in[8];
    float* out = (float*)d_out;

    dim3 gQKV(DD / 64, (BB * SS) / 128, 3);     // 16 x 32 x 3
    qkv_gemm_kernel<<<gQKV, 256>>>(x, Wq, bq, Wk, bk, Wv, bv);

    dim3 gAtt(SS / 64, BB * HH);                // 16 x 64
    attn_kernel<<<gAtt, 256>>>();

    headsum_kernel<<<(BB * SS * DHH) / 256, 256>>>();

    ff_kernel<<<(BB * SS) / 4, 256>>>(Wf, bf, out);
}

// round 3
// speedup vs baseline: 1.4970x; 1.4970x over previous
#include <cuda_runtime.h>
#include <cuda_bf16.h>
#include <math.h>
#include <stdint.h>

#define BB  4
#define SS  1024
#define DD  1024
#define HH  16
#define DHH 64
#define NFLAT 3072   // q:0-1023, k:1024-2047, v:2048-3071

// ---- persistent scratch (no allocations allowed) ----
__device__ float g_q[BB*HH*SS*DHH];     // [bh][s][e]
__device__ float g_k[BB*HH*SS*DHH];
__device__ float g_v[BB*HH*SS*DHH];
__device__ float g_z[BB*HH*SS*DHH];     // per-head attention output
__device__ float g_sum[BB*SS*DHH];      // head-summed [t][e]

__device__ __nv_bfloat16 g_xhi[BB*SS*DD];
__device__ __nv_bfloat16 g_xlo[BB*SS*DD];
__device__ __nv_bfloat16 g_whi[NFLAT*DD];   // transposed: [n][k]
__device__ __nv_bfloat16 g_wlo[NFLAT*DD];

// ============================================================
// helpers
// ============================================================
__device__ __forceinline__ uint32_t smem_u32(const void* p) {
    uint32_t a;
    asm("{ .reg .u64 t; cvta.to.shared.u64 t, %1; cvt.u32.u64 %0, t; }"
        : "=r"(a) : "l"(p));
    return a;
}

#define CP16(dst, src) \
    asm volatile("cp.async.cg.shared.global [%0], [%1], 16;" \
                 :: "r"(dst), "l"(src) : "memory")
#define CP_COMMIT() asm volatile("cp.async.commit_group;" ::: "memory")
#define CP_WAIT1()  asm volatile("cp.async.wait_group 1;" ::: "memory")
#define CP_WAIT0()  asm volatile("cp.async.wait_group 0;" ::: "memory")

#define LDSM_X4(R, addr) \
    asm volatile("ldmatrix.sync.aligned.m8n8.x4.shared.b16 {%0,%1,%2,%3}, [%4];" \
                 : "=r"((R)[0]), "=r"((R)[1]), "=r"((R)[2]), "=r"((R)[3]) \
                 : "r"(addr))

#define MMA16816(D, A, B) \
    asm volatile("mma.sync.aligned.m16n8k16.row.col.f32.bf16.bf16.f32 " \
                 "{%0,%1,%2,%3}, {%4,%5,%6,%7}, {%8,%9}, {%0,%1,%2,%3};" \
                 : "+f"((D)[0]), "+f"((D)[1]), "+f"((D)[2]), "+f"((D)[3]) \
                 : "r"((A)[0]), "r"((A)[1]), "r"((A)[2]), "r"((A)[3]), \
                   "r"((B)[0]), "r"((B)[1]))

// ============================================================
// Split x -> bf16 hi/lo
// ============================================================
__global__ __launch_bounds__(256) void split_x_kernel(const float* __restrict__ x)
{
    int i4 = blockIdx.x * 256 + threadIdx.x;     // over 1M float4
    float4 v = ((const float4*)x)[i4];
    __nv_bfloat16 h0 = __float2bfloat16(v.x);
    __nv_bfloat16 h1 = __float2bfloat16(v.y);
    __nv_bfloat16 h2 = __float2bfloat16(v.z);
    __nv_bfloat16 h3 = __float2bfloat16(v.w);
    __nv_bfloat16 l0 = __float2bfloat16(v.x - __bfloat162float(h0));
    __nv_bfloat16 l1 = __float2bfloat16(v.y - __bfloat162float(h1));
    __nv_bfloat16 l2 = __float2bfloat16(v.z - __bfloat162float(h2));
    __nv_bfloat16 l3 = __float2bfloat16(v.w - __bfloat162float(h3));
    __nv_bfloat162* ph = (__nv_bfloat162*)g_xhi;
    __nv_bfloat162* pl = (__nv_bfloat162*)g_xlo;
    ph[i4 * 2]     = __nv_bfloat162(h0, h1);
    ph[i4 * 2 + 1] = __nv_bfloat162(h2, h3);
    pl[i4 * 2]     = __nv_bfloat162(l0, l1);
    pl[i4 * 2 + 1] = __nv_bfloat162(l2, l3);
}

// ============================================================
// Split + transpose W -> g_whi/g_wlo [n=3072][k=1024]
// ============================================================
__global__ __launch_bounds__(256) void split_w_kernel(
    const float* __restrict__ Wq, const float* __restrict__ Wk,
    const float* __restrict__ Wv)
{
    __shared__ float ts[64][65];
    const int bid = blockIdx.x;
    const int hf = bid >> 4;          // 0..47
    const int kc = bid & 15;
    const int t = hf >> 4;            // 0..2
    const int h = hf & 15;
    const int k0 = kc * 64;
    const int tid = threadIdx.x;
    const float* W = (t == 0 ? Wq : (t == 1 ? Wk : Wv)) + (size_t)h * DD * DHH;

    #pragma unroll
    for (int j = 0; j < 16; j++) {
        int lin = j * 256 + tid;
        int kk = lin >> 6, e = lin & 63;
        ts[kk][e] = W[(size_t)(k0 + kk) * DHH + e];
    }
    __syncthreads();
    #pragma unroll
    for (int j = 0; j < 16; j++) {
        int lin = j * 256 + tid;
        int e = lin >> 6, kk = lin & 63;
        float v = ts[kk][e];
        __nv_bfloat16 hi = __float2bfloat16(v);
        __nv_bfloat16 lo = __float2bfloat16(v - __bfloat162float(hi));
        size_t o = ((size_t)(t * 1024 + h * 64 + e)) * DD + k0 + kk;
        g_whi[o] = hi;
        g_wlo[o] = lo;
    }
}

// ============================================================
// QKV projection via mma.sync bf16, 3x split (hh + hl + lh).
// CTA tile M=128 x N=128, BK=32, 8 warps (each 64x32), cp.async x2 stages.
// smem per stage: Ah,Al,Bh,Bl each 128x32 bf16 (8KB) = 32KB; 64KB total.
// A/B smem rows are 64B; 16B chunks swizzled: c ^= (r>>1)&3.
// ============================================================
#define T_AH 0u
#define T_AL 8192u
#define T_BH 16384u
#define T_BL 24576u
#define STAGE_BYTES 32768u

__device__ __forceinline__ void qkv_load_stage(uint32_t sb, int stage,
                                               int m0, int n0, int k0)
{
    const int tid = threadIdx.x;
    const char* pAh = (const char*)g_xhi;
    const char* pAl = (const char*)g_xlo;
    const char* pBh = (const char*)g_whi;
    const char* pBl = (const char*)g_wlo;
    uint32_t base = sb + stage * STAGE_BYTES;
    #pragma unroll
    for (int i = 0; i < 2; i++) {
        int chunk = tid + i * 256;            // 0..511
        int r = chunk >> 2;
        int c = chunk & 3;
        uint32_t off = r * 64 + (((uint32_t)(c ^ ((r >> 1) & 3))) << 4);
        size_t ga = ((size_t)(m0 + r) * DD + k0) * 2 + c * 16;
        size_t gb = ((size_t)(n0 + r) * DD + k0) * 2 + c * 16;
        CP16(base + T_AH + off, pAh + ga);
        CP16(base + T_AL + off, pAl + ga);
        CP16(base + T_BH + off, pBh + gb);
        CP16(base + T_BL + off, pBl + gb);
    }
}

__global__ __launch_bounds__(256) void qkv_mma_kernel(
    const float* __restrict__ bq, const float* __restrict__ bk,
    const float* __restrict__ bv)
{
    extern __shared__ char dsm[];
    const uint32_t sb = smem_u32(dsm);

    const int tid = threadIdx.x;
    const int wid = tid >> 5;
    const int lane = tid & 31;
    const int warp_m = wid >> 2;     // 0..1
    const int warp_n = wid & 3;      // 0..3
    const int n0 = blockIdx.x * 128;
    const int m0 = blockIdx.y * 128;

    float acc[4][4][4];
    #pragma unroll
    for (int i = 0; i < 4; i++)
        #pragma unroll
        for (int j = 0; j < 4; j++)
            #pragma unroll
            for (int v = 0; v < 4; v++) acc[i][j][v] = 0.f;

    qkv_load_stage(sb, 0, m0, n0, 0);
    CP_COMMIT();

    for (int kb = 0; kb < 32; kb++) {
        if (kb < 31) {
            qkv_load_stage(sb, (kb + 1) & 1, m0, n0, (kb + 1) * 32);
            CP_COMMIT();
            CP_WAIT1();
        } else {
            CP_WAIT0();
        }
        __syncthreads();

        const uint32_t stg = sb + (kb & 1) * STAGE_BYTES;
        #pragma unroll
        for (int s = 0; s < 2; s++) {
            // ---- A fragments (hi & lo), 4 m16 tiles ----
            uint32_t ah[16], al[16];
            #pragma unroll
            for (int mt = 0; mt < 4; mt++) {
                int r = warp_m * 64 + mt * 16 + (lane & 15);
                int c = 2 * s + (lane >> 4);
                uint32_t off = r * 64 + (((uint32_t)(c ^ ((r >> 1) & 3))) << 4);
                LDSM_X4(&ah[mt * 4], stg + T_AH + off);
                LDSM_X4(&al[mt * 4], stg + T_AL + off);
            }
            // ---- B fragments (hi & lo), 4 n8 tiles via 2 x4 loads ----
            uint32_t bh[8], bl[8];
            #pragma unroll
            for (int bt = 0; bt < 2; bt++) {
                int nr = warp_n * 32 + bt * 16 + ((lane >> 4) << 3) + (lane & 7);
                int c = 2 * s + ((lane >> 3) & 1);
                uint32_t off = nr * 64 + (((uint32_t)(c ^ ((nr >> 1) & 3))) << 4);
                LDSM_X4(&bh[bt * 4], stg + T_BH + off);
                LDSM_X4(&bl[bt * 4], stg + T_BL + off);
            }
            // ---- 3 products ----
            #pragma unroll
            for (int mt = 0; mt < 4; mt++)
                #pragma unroll
                for (int nt = 0; nt < 4; nt++) {
                    int bi = (nt >> 1) * 4 + (nt & 1) * 2;
                    MMA16816(acc[mt][nt], &ah[mt * 4], &bh[bi]);
                    MMA16816(acc[mt][nt], &ah[mt * 4], &bl[bi]);
                    MMA16816(acc[mt][nt], &al[mt * 4], &bh[bi]);
                }
        }
        __syncthreads();
    }

    // ---- epilogue: bias + scatter to g_q/g_k/g_v head-major layout ----
    #pragma unroll
    for (int nt = 0; nt < 4; nt++) {
        int n = n0 + warp_n * 32 + nt * 8 + (lane & 3) * 2;
        int t = n >> 10;
        int h = (n >> 6) & 15;
        int e = n & 63;
        const float* bias = (t == 0 ? bq : (t == 1 ? bk : bv));
        float* outp = (t == 0 ? g_q : (t == 1 ? g_k : g_v));
        float b0v = bias[h * 64 + e];
        float b1v = bias[h * 64 + e + 1];
        #pragma unroll
        for (int mt = 0; mt < 4; mt++) {
            #pragma unroll
            for (int half = 0; half < 2; half++) {
                int row = m0 + warp_m * 64 + mt * 16 + (lane >> 2) + half * 8;
                int b = row >> 10;
                int s = row & 1023;
                float2 r2;
                r2.x = acc[mt][nt][half * 2]     + b0v;
                r2.y = acc[mt][nt][half * 2 + 1] + b1v;
                *(float2*)&outp[((size_t)(b * HH + h) * SS + s) * DHH + e] = r2;
            }
        }
    }
}

// ============================================================
// Flash attention, causal, per (q-tile of 64, head). 256 threads.
// ============================================================
__global__ __launch_bounds__(256) void attn_kernel()
{
    __shared__ float Qt[64][64];
    __shared__ float Kt[64][64];
    __shared__ float Vs[64][64];

    const int qt = blockIdx.x;
    const int bh = blockIdx.y;
    const int q0 = qt * 64;
    const int tid = threadIdx.x;
    const int tx = tid & 15;
    const int ty = tid >> 4;

    const float* Qg = g_q + ((size_t)bh * SS + q0) * DHH;
    const float* Kg = g_k + (size_t)bh * SS * DHH;
    const float* Vg = g_v + (size_t)bh * SS * DHH;

    {
        const int lr = tid >> 4;
        const int lc = (tid & 15) * 4;
        #pragma unroll
        for (int c = 0; c < 4; c++) {
            int row = lr + c * 16;
            float4 v = *(const float4*)&Qg[(size_t)row * DHH + lc];
            Qt[lc + 0][row] = v.x;  Qt[lc + 1][row] = v.y;
            Qt[lc + 2][row] = v.z;  Qt[lc + 3][row] = v.w;
        }
    }

    float o[4][4];
    #pragma unroll
    for (int i = 0; i < 4; i++)
        #pragma unroll
        for (int j = 0; j < 4; j++) o[i][j] = 0.f;
    float mrow[4] = {-1e30f, -1e30f, -1e30f, -1e30f};
    float lrow[4] = {0.f, 0.f, 0.f, 0.f};

    for (int kt = 0; kt <= qt; kt++) {
        __syncthreads();
        {
            const int lr = tid >> 4;
            const int lc = (tid & 15) * 4;
            #pragma unroll
            for (int c = 0; c < 4; c++) {
                int row = lr + c * 16;
                float4 kk = *(const float4*)&Kg[((size_t)kt * 64 + row) * DHH + lc];
                float4 vv = *(const float4*)&Vg[((size_t)kt * 64 + row) * DHH + lc];
                Kt[lc + 0][row] = kk.x;  Kt[lc + 1][row] = kk.y;
                Kt[lc + 2][row] = kk.z;  Kt[lc + 3][row] = kk.w;
                *(float4*)&Vs[row][lc] = vv;
            }
        }
        __syncthreads();

        float s[4][4];
        #pragma unroll
        for (int i = 0; i < 4; i++)
            #pragma unroll
            for (int j = 0; j < 4; j++) s[i][j] = 0.f;
        #pragma unroll 16
        for (int e = 0; e < 64; e++) {
            float4 a = *(const float4*)&Qt[e][ty * 4];
            float4 b = *(const float4*)&Kt[e][tx * 4];
            s[0][0] += a.x * b.x; s[0][1] += a.x * b.y; s[0][2] += a.x * b.z; s[0][3] += a.x * b.w;
            s[1][0] += a.y * b.x; s[1][1] += a.y * b.y; s[1][2] += a.y * b.z; s[1][3] += a.y * b.w;
            s[2][0] += a.z * b.x; s[2][1] += a.z * b.y; s[2][2] += a.z * b.z; s[2][3] += a.z * b.w;
            s[3][0] += a.w * b.x; s[3][1] += a.w * b.y; s[3][2] += a.w * b.z; s[3][3] += a.w * b.w;
        }

        #pragma unroll
        for (int i = 0; i < 4; i++) {
            const int gr = q0 + ty * 4 + i;
            float mnew = mrow[i];
            #pragma unroll
            for (int j = 0; j < 4; j++) {
                float v = s[i][j] * 0.125f;
                int gc = kt * 64 + tx * 4 + j;
                if (gc > gr) v -= 1e11f;
                s[i][j] = v;
                mnew = fmaxf(mnew, v);
            }
            #pragma unroll
            for (int d = 8; d > 0; d >>= 1)
                mnew = fmaxf(mnew, __shfl_xor_sync(0xffffffffu, mnew, d));
            float alpha = expf(mrow[i] - mnew);
            mrow[i] = mnew;
            float rs = 0.f;
            #pragma unroll
            for (int j = 0; j < 4; j++) {
                s[i][j] = expf(s[i][j] - mnew);
                rs += s[i][j];
            }
            #pragma unroll
            for (int d = 8; d > 0; d >>= 1)
                rs += __shfl_xor_sync(0xffffffffu, rs, d);
            lrow[i] = lrow[i] * alpha + rs;
            #pragma unroll
            for (int j = 0; j < 4; j++) o[i][j] *= alpha;
        }

        __syncthreads();
        #pragma unroll
        for (int i = 0; i < 4; i++)
            #pragma unroll
            for (int j = 0; j < 4; j++)
                Kt[tx * 4 + j][ty * 4 + i] = s[i][j];
        __syncthreads();

        #pragma unroll 16
        for (int k = 0; k < 64; k++) {
            float4 p = *(const float4*)&Kt[k][ty * 4];
            float4 v = *(const float4*)&Vs[k][tx * 4];
            o[0][0] += p.x * v.x; o[0][1] += p.x * v.y; o[0][2] += p.x * v.z; o[0][3] += p.x * v.w;
            o[1][0] += p.y * v.x; o[1][1] += p.y * v.y; o[1][2] += p.y * v.z; o[1][3] += p.y * v.w;
            o[2][0] += p.z * v.x; o[2][1] += p.z * v.y; o[2][2] += p.z * v.z; o[2][3] += p.z * v.w;
            o[3][0] += p.w * v.x; o[3][1] += p.w * v.y; o[3][2] += p.w * v.z; o[3][3] += p.w * v.w;
        }
    }

    float* Zg = g_z + ((size_t)bh * SS + q0) * DHH;
    #pragma unroll
    for (int i = 0; i < 4; i++) {
        float inv = 1.f / lrow[i];
        float4 r;
        r.x = o[i][0] * inv;  r.y = o[i][1] * inv;
        r.z = o[i][2] * inv;  r.w = o[i][3] * inv;
        *(float4*)&Zg[(size_t)(ty * 4 + i) * DHH + tx * 4] = r;
    }
}

// ============================================================
__global__ __launch_bounds__(256) void headsum_kernel()
{
    int idx = blockIdx.x * blockDim.x + threadIdx.x;
    int e = idx & 63;
    int s = (idx >> 6) & 1023;
    int b = idx >> 16;
    const float* zp = g_z + ((size_t)(b * HH) * SS + s) * DHH + e;
    float acc = 0.f;
    #pragma unroll
    for (int h = 0; h < HH; h++) acc += zp[(size_t)h * SS * DHH];
    g_sum[idx] = acc;
}

// ============================================================
__device__ __forceinline__ float gelu_exact(float v)
{
    return 0.5f * v * (1.0f + erff(v * 0.70710678118654752f));
}

__global__ __launch_bounds__(256) void ff_kernel(const float* __restrict__ Wf,
                                                 const float* __restrict__ bf,
                                                 float* __restrict__ out)
{
    __shared__ float ssum[4][64];
    const int t0 = blockIdx.x * 4;
    const int tid = threadIdx.x;

    ssum[tid >> 6][tid & 63] = g_sum[(size_t)(t0 + (tid >> 6)) * DHH + (tid & 63)];
    __syncthreads();

    const int col = tid * 4;
    float acc[4][4];
    #pragma unroll
    for (int t = 0; t < 4; t++)
        #pragma unroll
        for (int j = 0; j < 4; j++) acc[t][j] = 0.f;

    #pragma unroll 8
    for (int e = 0; e < 64; e++) {
        float4 w = *(const float4*)&Wf[(size_t)e * DD + col];
        #pragma unroll
        for (int t = 0; t < 4; t++) {
            float sv = ssum[t][e];
            acc[t][0] += sv * w.x;
            acc[t][1] += sv * w.y;
            acc[t][2] += sv * w.z;
            acc[t][3] += sv * w.w;
        }
    }

    float4 b4 = *(const float4*)&bf[col];
    #pragma unroll
    for (int t = 0; t < 4; t++) {
        float4 r;
        r.x = gelu_exact(acc[t][0] + b4.x);
        r.y = gelu_exact(acc[t][1] + b4.y);
        r.z = gelu_exact(acc[t][2] + b4.z);
        r.w = gelu_exact(acc[t][3] + b4.w);
        *(float4*)&out[(size_t)(t0 + t) * DD + col] = r;
    }
}

// ============================================================
extern "C" void kernel_launch(void* const* d_in, const int* in_sizes, int n_in,
                              void* d_out, int out_size)
{
    const float* x  = (const float*)d_in[0];
    const float* Wq = (const float*)d_in[1];
    const float* bq = (const float*)d_in[2];
    const float* Wk = (const float*)d_in[3];
    const float* bk = (const float*)d_in[4];
    const float* Wv = (const float*)d_in[5];
    const float* bv = (const float*)d_in[6];
    const float* Wf = (const float*)d_in[7];
    const float* bf = (const float*)d_in[8];
    float* out = (float*)d_out;

    static const int QKV_SMEM = 65536;     // 2 stages x 32KB
    cudaFuncSetAttribute(qkv_mma_kernel,
                         cudaFuncAttributeMaxDynamicSharedMemorySize, QKV_SMEM);

    split_x_kernel<<<(BB * SS * DD) / 4 / 256, 256>>>(x);
    split_w_kernel<<<48 * 16, 256>>>(Wq, Wk, Wv);

    dim3 gMMA(NFLAT / 128, (BB * SS) / 128);       // 24 x 32
    qkv_mma_kernel<<<gMMA, 256, QKV_SMEM>>>(bq, bk, bv);

    dim3 gAtt(SS / 64, BB * HH);
    attn_kernel<<<gAtt, 256>>>();

    headsum_kernel<<<(BB * SS * DHH) / 256, 256>>>();

    ff_kernel<<<(BB * SS) / 4, 256>>>(Wf, bf, out);
}

// round 4
// speedup vs baseline: 1.9334x; 1.2915x over previous
#include <cuda_runtime.h>
#include <cuda_bf16.h>
#include <math.h>
#include <stdint.h>

#define BB  4
#define SS  1024
#define DD  1024
#define HH  16
#define DHH 64
#define NFLAT 3072   // q:0-1023, k:1024-2047, v:2048-3071
#define LOG2E 1.4426950408889634f

// ---- persistent scratch (no allocations allowed) ----
__device__ float g_z[BB*HH*SS*DHH];     // per-head attention output
__device__ float g_sum[BB*SS*DHH];      // head-summed [t][e]

__device__ __nv_bfloat16 g_xhi[BB*SS*DD];
__device__ __nv_bfloat16 g_xlo[BB*SS*DD];
__device__ __nv_bfloat16 g_whi[NFLAT*DD];   // transposed: [n][k]
__device__ __nv_bfloat16 g_wlo[NFLAT*DD];

// attention operands, hi/lo split bf16
__device__ __nv_bfloat16 g_qhi[64*SS*DHH];   // [bh][s][e]
__device__ __nv_bfloat16 g_qlo[64*SS*DHH];
__device__ __nv_bfloat16 g_khi[64*SS*DHH];
__device__ __nv_bfloat16 g_klo[64*SS*DHH];
__device__ __nv_bfloat16 g_vthi[64*DHH*SS];  // [bh][e][s]  (transposed)
__device__ __nv_bfloat16 g_vtlo[64*DHH*SS];

// ============================================================
// helpers
// ============================================================
__device__ __forceinline__ uint32_t smem_u32(const void* p) {
    uint32_t a;
    asm("{ .reg .u64 t; cvta.to.shared.u64 t, %1; cvt.u32.u64 %0, t; }"
        : "=r"(a) : "l"(p));
    return a;
}

#define CP16(dst, src) \
    asm volatile("cp.async.cg.shared.global [%0], [%1], 16;" \
                 :: "r"(dst), "l"(src) : "memory")
#define CP_COMMIT() asm volatile("cp.async.commit_group;" ::: "memory")
#define CP_WAIT1()  asm volatile("cp.async.wait_group 1;" ::: "memory")
#define CP_WAIT0()  asm volatile("cp.async.wait_group 0;" ::: "memory")

#define LDSM_X4(R, addr) \
    asm volatile("ldmatrix.sync.aligned.m8n8.x4.shared.b16 {%0,%1,%2,%3}, [%4];" \
                 : "=r"((R)[0]), "=r"((R)[1]), "=r"((R)[2]), "=r"((R)[3]) \
                 : "r"(addr))

#define MMA16816(D, A, B) \
    asm volatile("mma.sync.aligned.m16n8k16.row.col.f32.bf16.bf16.f32 " \
                 "{%0,%1,%2,%3}, {%4,%5,%6,%7}, {%8,%9}, {%0,%1,%2,%3};" \
                 : "+f"((D)[0]), "+f"((D)[1]), "+f"((D)[2]), "+f"((D)[3]) \
                 : "r"((A)[0]), "r"((A)[1]), "r"((A)[2]), "r"((A)[3]), \
                   "r"((B)[0]), "r"((B)[1]))

// pack two f32 into bf16x2 reg: {hi = b (col+1), lo = a (col)}
__device__ __forceinline__ uint32_t pack_bf16x2(float a, float b) {
    uint32_t r;
    asm("cvt.rn.bf16x2.f32 %0, %1, %2;" : "=r"(r) : "f"(b), "f"(a));
    return r;
}

// ============================================================
// Split x -> bf16 hi/lo
// ============================================================
__global__ __launch_bounds__(256) void split_x_kernel(const float* __restrict__ x)
{
    int i4 = blockIdx.x * 256 + threadIdx.x;
    float4 v = ((const float4*)x)[i4];
    __nv_bfloat16 h0 = __float2bfloat16(v.x);
    __nv_bfloat16 h1 = __float2bfloat16(v.y);
    __nv_bfloat16 h2 = __float2bfloat16(v.z);
    __nv_bfloat16 h3 = __float2bfloat16(v.w);
    __nv_bfloat16 l0 = __float2bfloat16(v.x - __bfloat162float(h0));
    __nv_bfloat16 l1 = __float2bfloat16(v.y - __bfloat162float(h1));
    __nv_bfloat16 l2 = __float2bfloat16(v.z - __bfloat162float(h2));
    __nv_bfloat16 l3 = __float2bfloat16(v.w - __bfloat162float(h3));
    __nv_bfloat162* ph = (__nv_bfloat162*)g_xhi;
    __nv_bfloat162* pl = (__nv_bfloat162*)g_xlo;
    ph[i4 * 2]     = __nv_bfloat162(h0, h1);
    ph[i4 * 2 + 1] = __nv_bfloat162(h2, h3);
    pl[i4 * 2]     = __nv_bfloat162(l0, l1);
    pl[i4 * 2 + 1] = __nv_bfloat162(l2, l3);
}

// ============================================================
// Split + transpose W -> g_whi/g_wlo [n=3072][k=1024]
// ============================================================
__global__ __launch_bounds__(256) void split_w_kernel(
    const float* __restrict__ Wq, const float* __restrict__ Wk,
    const float* __restrict__ Wv)
{
    __shared__ float ts[64][65];
    const int bid = blockIdx.x;
    const int hf = bid >> 4;
    const int kc = bid & 15;
    const int t = hf >> 4;
    const int h = hf & 15;
    const int k0 = kc * 64;
    const int tid = threadIdx.x;
    const float* W = (t == 0 ? Wq : (t == 1 ? Wk : Wv)) + (size_t)h * DD * DHH;

    #pragma unroll
    for (int j = 0; j < 16; j++) {
        int lin = j * 256 + tid;
        int kk = lin >> 6, e = lin & 63;
        ts[kk][e] = W[(size_t)(k0 + kk) * DHH + e];
    }
    __syncthreads();
    #pragma unroll
    for (int j = 0; j < 16; j++) {
        int lin = j * 256 + tid;
        int e = lin >> 6, kk = lin & 63;
        float v = ts[kk][e];
        __nv_bfloat16 hi = __float2bfloat16(v);
        __nv_bfloat16 lo = __float2bfloat16(v - __bfloat162float(hi));
        size_t o = ((size_t)(t * 1024 + h * 64 + e)) * DD + k0 + kk;
        g_whi[o] = hi;
        g_wlo[o] = lo;
    }
}

// ============================================================
// QKV projection via mma.sync bf16, 3x split.
// Epilogue writes bf16 hi/lo: Q,K k-major; V transposed [bh][e][s].
// ============================================================
#define T_AH 0u
#define T_AL 8192u
#define T_BH 16384u
#define T_BL 24576u
#define STAGE_BYTES 32768u

__device__ __forceinline__ void qkv_load_stage(uint32_t sb, int stage,
                                               int m0, int n0, int k0)
{
    const int tid = threadIdx.x;
    const char* pAh = (const char*)g_xhi;
    const char* pAl = (const char*)g_xlo;
    const char* pBh = (const char*)g_whi;
    const char* pBl = (const char*)g_wlo;
    uint32_t base = sb + stage * STAGE_BYTES;
    #pragma unroll
    for (int i = 0; i < 2; i++) {
        int chunk = tid + i * 256;
        int r = chunk >> 2;
        int c = chunk & 3;
        uint32_t off = r * 64 + (((uint32_t)(c ^ ((r >> 1) & 3))) << 4);
        size_t ga = ((size_t)(m0 + r) * DD + k0) * 2 + c * 16;
        size_t gb = ((size_t)(n0 + r) * DD + k0) * 2 + c * 16;
        CP16(base + T_AH + off, pAh + ga);
        CP16(base + T_AL + off, pAl + ga);
        CP16(base + T_BH + off, pBh + gb);
        CP16(base + T_BL + off, pBl + gb);
    }
}

__global__ __launch_bounds__(256) void qkv_mma_kernel(
    const float* __restrict__ bq, const float* __restrict__ bk,
    const float* __restrict__ bv)
{
    extern __shared__ char dsm[];
    const uint32_t sb = smem_u32(dsm);

    const int tid = threadIdx.x;
    const int wid = tid >> 5;
    const int lane = tid & 31;
    const int warp_m = wid >> 2;
    const int warp_n = wid & 3;
    const int n0 = blockIdx.x * 128;
    const int m0 = blockIdx.y * 128;

    float acc[4][4][4];
    #pragma unroll
    for (int i = 0; i < 4; i++)
        #pragma unroll
        for (int j = 0; j < 4; j++)
            #pragma unroll
            for (int v = 0; v < 4; v++) acc[i][j][v] = 0.f;

    qkv_load_stage(sb, 0, m0, n0, 0);
    CP_COMMIT();

    for (int kb = 0; kb < 32; kb++) {
        if (kb < 31) {
            qkv_load_stage(sb, (kb + 1) & 1, m0, n0, (kb + 1) * 32);
            CP_COMMIT();
            CP_WAIT1();
        } else {
            CP_WAIT0();
        }
        __syncthreads();

        const uint32_t stg = sb + (kb & 1) * STAGE_BYTES;
        #pragma unroll
        for (int s = 0; s < 2; s++) {
            uint32_t ah[16], al[16];
            #pragma unroll
            for (int mt = 0; mt < 4; mt++) {
                int r = warp_m * 64 + mt * 16 + (lane & 15);
                int c = 2 * s + (lane >> 4);
                uint32_t off = r * 64 + (((uint32_t)(c ^ ((r >> 1) & 3))) << 4);
                LDSM_X4(&ah[mt * 4], stg + T_AH + off);
                LDSM_X4(&al[mt * 4], stg + T_AL + off);
            }
            uint32_t bh[8], bl[8];
            #pragma unroll
            for (int bt = 0; bt < 2; bt++) {
                int nr = warp_n * 32 + bt * 16 + ((lane >> 4) << 3) + (lane & 7);
                int c = 2 * s + ((lane >> 3) & 1);
                uint32_t off = nr * 64 + (((uint32_t)(c ^ ((nr >> 1) & 3))) << 4);
                LDSM_X4(&bh[bt * 4], stg + T_BH + off);
                LDSM_X4(&bl[bt * 4], stg + T_BL + off);
            }
            #pragma unroll
            for (int mt = 0; mt < 4; mt++)
                #pragma unroll
                for (int nt = 0; nt < 4; nt++) {
                    int bi = (nt >> 1) * 4 + (nt & 1) * 2;
                    MMA16816(acc[mt][nt], &ah[mt * 4], &bh[bi]);
                    MMA16816(acc[mt][nt], &ah[mt * 4], &bl[bi]);
                    MMA16816(acc[mt][nt], &al[mt * 4], &bh[bi]);
                }
        }
        __syncthreads();
    }

    // ---- epilogue: bias, hi/lo split, scatter ----
    #pragma unroll
    for (int nt = 0; nt < 4; nt++) {
        int n = n0 + warp_n * 32 + nt * 8 + (lane & 3) * 2;
        int t = n >> 10;
        int h = (n >> 6) & 15;
        int e = n & 63;
        const float* bias = (t == 0 ? bq : (t == 1 ? bk : bv));
        float b0v = bias[h * 64 + e];
        float b1v = bias[h * 64 + e + 1];
        #pragma unroll
        for (int mt = 0; mt < 4; mt++) {
            #pragma unroll
            for (int half = 0; half < 2; half++) {
                int row = m0 + warp_m * 64 + mt * 16 + (lane >> 2) + half * 8;
                int b = row >> 10;
                int s = row & 1023;
                int bh = b * HH + h;
                float v0 = acc[mt][nt][half * 2]     + b0v;
                float v1 = acc[mt][nt][half * 2 + 1] + b1v;
                __nv_bfloat16 h0 = __float2bfloat16(v0);
                __nv_bfloat16 h1 = __float2bfloat16(v1);
                __nv_bfloat16 l0 = __float2bfloat16(v0 - __bfloat162float(h0));
                __nv_bfloat16 l1 = __float2bfloat16(v1 - __bfloat162float(h1));
                if (t == 0) {
                    size_t o = ((size_t)(bh << 10) + s) * 64 + e;
                    *(__nv_bfloat162*)&g_qhi[o] = __nv_bfloat162(h0, h1);
                    *(__nv_bfloat162*)&g_qlo[o] = __nv_bfloat162(l0, l1);
                } else if (t == 1) {
                    size_t o = ((size_t)(bh << 10) + s) * 64 + e;
                    *(__nv_bfloat162*)&g_khi[o] = __nv_bfloat162(h0, h1);
                    *(__nv_bfloat162*)&g_klo[o] = __nv_bfloat162(l0, l1);
                } else {
                    size_t o = ((size_t)(bh * 64 + e) << 10) + s;
                    g_vthi[o] = h0;          g_vtlo[o] = l0;
                    g_vthi[o + 1024] = h1;   g_vtlo[o + 1024] = l1;
                }
            }
        }
    }
}

// ============================================================
// Flash attention via mma.sync, hi/lo split everywhere.
// CTA: 128 q-rows x one bh. 8 warps x 16 rows. KT=64 tiles, double-buffered.
// smem: Qh/Ql 16KB each + 2 stages x (Kh,Kl,Vh,Vl = 32KB) = 96KB.
// ============================================================
#define AQ_H 0u
#define AQ_L 16384u
#define AST  32768u
#define AST_SZ 32768u
// within a stage: KH 0, KL 8192, VH 16384, VL 24576

__device__ __forceinline__ void attn_load_kv(uint32_t stg, int bh, int k0)
{
    const int tid = threadIdx.x;
    const char* kh = (const char*)g_khi;
    const char* kl = (const char*)g_klo;
    const char* vh = (const char*)g_vthi;
    const char* vl = (const char*)g_vtlo;
    #pragma unroll
    for (int i = 0; i < 2; i++) {
        int ch = i * 256 + tid;        // 0..511
        int r = ch >> 3;               // 0..63
        int c = ch & 7;
        uint32_t off = r * 128 + (((uint32_t)(c ^ (r & 7))) << 4);
        size_t ksrc = ((size_t)((bh << 10) + k0 + r)) * 128 + c * 16;
        size_t vsrc = ((size_t)(bh * 64 + r) << 11) + k0 * 2 + c * 16;
        CP16(stg + 0 + off, kh + ksrc);
        CP16(stg + 8192 + off, kl + ksrc);
        CP16(stg + 16384 + off, vh + vsrc);
        CP16(stg + 24576 + off, vl + vsrc);
    }
}

__global__ __launch_bounds__(256) void attn_mma_kernel()
{
    extern __shared__ char dsm[];
    const uint32_t sb = smem_u32(dsm);

    const int tid = threadIdx.x;
    const int wid = tid >> 5;
    const int lane = tid & 31;
    const int qt = 7 - blockIdx.x;     // heavy tiles first
    const int bh = blockIdx.y;
    const int q0 = qt * 128;
    const int n_kt = 2 * qt + 2;

    // ---- issue Q loads + stage 0 ----
    {
        const char* qh = (const char*)g_qhi;
        const char* ql = (const char*)g_qlo;
        #pragma unroll
        for (int i = 0; i < 4; i++) {
            int ch = i * 256 + tid;    // 0..1023
            int r = ch >> 3;           // 0..127
            int c = ch & 7;
            uint32_t off = r * 128 + (((uint32_t)(c ^ (r & 7))) << 4);
            size_t src = ((size_t)((bh << 10) + q0 + r)) * 128 + c * 16;
            CP16(sb + AQ_H + off, qh + src);
            CP16(sb + AQ_L + off, ql + src);
        }
        attn_load_kv(sb + AST, bh, 0);
        CP_COMMIT();
    }

    float o[8][4];
    #pragma unroll
    for (int i = 0; i < 8; i++)
        #pragma unroll
        for (int j = 0; j < 4; j++) o[i][j] = 0.f;
    float m[2] = {-1e30f, -1e30f};
    float l[2] = {0.f, 0.f};
    uint32_t qfh[16], qfl[16];
    const int wr0 = q0 + wid * 16;

    for (int kt = 0; kt < n_kt; kt++) {
        if (kt + 1 < n_kt) {
            attn_load_kv(sb + AST + ((kt + 1) & 1) * AST_SZ, bh, (kt + 1) * 64);
            CP_COMMIT();
            CP_WAIT1();
        } else {
            CP_WAIT0();
        }
        __syncthreads();

        if (kt == 0) {       // Q fragments once, kept in registers
            #pragma unroll
            for (int ks = 0; ks < 4; ks++) {
                int r = wid * 16 + (lane & 15);
                int c = 2 * ks + (lane >> 4);
                uint32_t off = r * 128 + (((uint32_t)(c ^ (r & 7))) << 4);
                LDSM_X4(&qfh[ks * 4], sb + AQ_H + off);
                LDSM_X4(&qfl[ks * 4], sb + AQ_L + off);
            }
        }

        const int k0 = kt * 64;
        const bool skip = (k0 > wr0 + 15);
        if (!skip) {
            const uint32_t stg = sb + AST + (kt & 1) * AST_SZ;
            // ---- S = Q K^T ----
            float sc[8][4];
            #pragma unroll
            for (int i = 0; i < 8; i++)
                #pragma unroll
                for (int j = 0; j < 4; j++) sc[i][j] = 0.f;
            #pragma unroll
            for (int ks = 0; ks < 4; ks++) {
                uint32_t kfh[16], kfl[16];
                #pragma unroll
                for (int nt2 = 0; nt2 < 4; nt2++) {
                    int nr = nt2 * 16 + ((lane >> 4) << 3) + (lane & 7);
                    int c = 2 * ks + ((lane >> 3) & 1);
                    uint32_t off = nr * 128 + (((uint32_t)(c ^ (nr & 7))) << 4);
                    LDSM_X4(&kfh[nt2 * 4], stg + 0 + off);
                    LDSM_X4(&kfl[nt2 * 4], stg + 8192 + off);
                }
                #pragma unroll
                for (int nt = 0; nt < 8; nt++) {
                    int bi = (nt >> 1) * 4 + (nt & 1) * 2;
                    MMA16816(sc[nt], &qfh[ks * 4], &kfh[bi]);
                    MMA16816(sc[nt], &qfh[ks * 4], &kfl[bi]);
                    MMA16816(sc[nt], &qfl[ks * 4], &kfh[bi]);
                }
            }
            // ---- online softmax ----
            const bool need_mask = (k0 + 63 > wr0);
            uint32_t ph[16], pl[16];
            float alpha[2];
            #pragma unroll
            for (int rs = 0; rs < 2; rs++) {
                int grow = wr0 + (lane >> 2) + rs * 8;
                float mx = -1e30f;
                #pragma unroll
                for (int nt = 0; nt < 8; nt++) {
                    float v0 = sc[nt][rs * 2] * 0.125f;
                    float v1 = sc[nt][rs * 2 + 1] * 0.125f;
                    if (need_mask) {
                        int gc = k0 + nt * 8 + 2 * (lane & 3);
                        if (gc > grow) v0 = -1e30f;
                        if (gc + 1 > grow) v1 = -1e30f;
                    }
                    sc[nt][rs * 2] = v0;
                    sc[nt][rs * 2 + 1] = v1;
                    mx = fmaxf(mx, fmaxf(v0, v1));
                }
                mx = fmaxf(mx, __shfl_xor_sync(0xffffffffu, mx, 1));
                mx = fmaxf(mx, __shfl_xor_sync(0xffffffffu, mx, 2));
                float mn = fmaxf(m[rs], mx);
                alpha[rs] = __expf(m[rs] - mn);
                m[rs] = mn;
                float rsum = 0.f;
                #pragma unroll
                for (int nt = 0; nt < 8; nt++) {
                    float p0 = __expf(sc[nt][rs * 2] - mn);
                    float p1 = __expf(sc[nt][rs * 2 + 1] - mn);
                    rsum += p0 + p1;
                    uint32_t hp = pack_bf16x2(p0, p1);
                    float r0 = p0 - __uint_as_float(hp << 16);
                    float r1 = p1 - __uint_as_float(hp & 0xFFFF0000u);
                    uint32_t lp = pack_bf16x2(r0, r1);
                    int idx = (nt >> 1) * 4 + (nt & 1) * 2 + rs;
                    ph[idx] = hp;
                    pl[idx] = lp;
                }
                rsum += __shfl_xor_sync(0xffffffffu, rsum, 1);
                rsum += __shfl_xor_sync(0xffffffffu, rsum, 2);
                l[rs] = l[rs] * alpha[rs] + rsum;
                #pragma unroll
                for (int ne = 0; ne < 8; ne++) {
                    o[ne][rs * 2] *= alpha[rs];
                    o[ne][rs * 2 + 1] *= alpha[rs];
                }
            }
            // ---- O += P V ----
            #pragma unroll
            for (int kp = 0; kp < 4; kp++) {
                uint32_t vfh[16], vfl[16];
                #pragma unroll
                for (int ne2 = 0; ne2 < 4; ne2++) {
                    int nr = ne2 * 16 + ((lane >> 4) << 3) + (lane & 7);
                    int c = 2 * kp + ((lane >> 3) & 1);
                    uint32_t off = nr * 128 + (((uint32_t)(c ^ (nr & 7))) << 4);
                    LDSM_X4(&vfh[ne2 * 4], stg + 16384 + off);
                    LDSM_X4(&vfl[ne2 * 4], stg + 24576 + off);
                }
                #pragma unroll
                for (int ne = 0; ne < 8; ne++) {
                    int bi = (ne >> 1) * 4 + (ne & 1) * 2;
                    MMA16816(o[ne], &ph[kp * 4], &vfh[bi]);
                    MMA16816(o[ne], &ph[kp * 4], &vfl[bi]);
                    MMA16816(o[ne], &pl[kp * 4], &vfh[bi]);
                }
            }
        }
        __syncthreads();
    }

    // ---- normalize + write ----
    #pragma unroll
    for (int rs = 0; rs < 2; rs++) {
        float inv = 1.f / l[rs];
        int row = wr0 + (lane >> 2) + rs * 8;
        #pragma unroll
        for (int ne = 0; ne < 8; ne++) {
            int e = ne * 8 + 2 * (lane & 3);
            float2 r2;
            r2.x = o[ne][rs * 2] * inv;
            r2.y = o[ne][rs * 2 + 1] * inv;
            *(float2*)&g_z[((size_t)(bh << 10) + row) * 64 + e] = r2;
        }
    }
}

// ============================================================
__global__ __launch_bounds__(256) void headsum_kernel()
{
    int idx = blockIdx.x * blockDim.x + threadIdx.x;
    int e = idx & 63;
    int s = (idx >> 6) & 1023;
    int b = idx >> 16;
    const float* zp = g_z + ((size_t)(b * HH) * SS + s) * DHH + e;
    float acc = 0.f;
    #pragma unroll
    for (int h = 0; h < HH; h++) acc += zp[(size_t)h * SS * DHH];
    g_sum[idx] = acc;
}

// ============================================================
__device__ __forceinline__ float gelu_exact(float v)
{
    return 0.5f * v * (1.0f + erff(v * 0.70710678118654752f));
}

__global__ __launch_bounds__(256) void ff_kernel(const float* __restrict__ Wf,
                                                 const float* __restrict__ bf,
                                                 float* __restrict__ out)
{
    __shared__ float ssum[4][64];
    const int t0 = blockIdx.x * 4;
    const int tid = threadIdx.x;

    ssum[tid >> 6][tid & 63] = g_sum[(size_t)(t0 + (tid >> 6)) * DHH + (tid & 63)];
    __syncthreads();

    const int col = tid * 4;
    float acc[4][4];
    #pragma unroll
    for (int t = 0; t < 4; t++)
        #pragma unroll
        for (int j = 0; j < 4; j++) acc[t][j] = 0.f;

    #pragma unroll 8
    for (int e = 0; e < 64; e++) {
        float4 w = *(const float4*)&Wf[(size_t)e * DD + col];
        #pragma unroll
        for (int t = 0; t < 4; t++) {
            float sv = ssum[t][e];
            acc[t][0] += sv * w.x;
            acc[t][1] += sv * w.y;
            acc[t][2] += sv * w.z;
            acc[t][3] += sv * w.w;
        }
    }

    float4 b4 = *(const float4*)&bf[col];
    #pragma unroll
    for (int t = 0; t < 4; t++) {
        float4 r;
        r.x = gelu_exact(acc[t][0] + b4.x);
        r.y = gelu_exact(acc[t][1] + b4.y);
        r.z = gelu_exact(acc[t][2] + b4.z);
        r.w = gelu_exact(acc[t][3] + b4.w);
        *(float4*)&out[(size_t)(t0 + t) * DD + col] = r;
    }
}

// ============================================================
extern "C" void kernel_launch(void* const* d_in, const int* in_sizes, int n_in,
                              void* d_out, int out_size)
{
    const float* x  = (const float*)d_in[0];
    const float* Wq = (const float*)d_in[1];
    const float* bq = (const float*)d_in[2];
    const float* Wk = (const float*)d_in[3];
    const float* bk = (const float*)d_in[4];
    const float* Wv = (const float*)d_in[5];
    const float* bv = (const float*)d_in[6];
    const float* Wf = (const float*)d_in[7];
    const float* bf = (const float*)d_in[8];
    float* out = (float*)d_out;

    static const int QKV_SMEM = 65536;
    static const int ATT_SMEM = 98304;
    cudaFuncSetAttribute(qkv_mma_kernel,
                         cudaFuncAttributeMaxDynamicSharedMemorySize, QKV_SMEM);
    cudaFuncSetAttribute(attn_mma_kernel,
                         cudaFuncAttributeMaxDynamicSharedMemorySize, ATT_SMEM);

    split_x_kernel<<<(BB * SS * DD) / 4 / 256, 256>>>(x);
    split_w_kernel<<<48 * 16, 256>>>(Wq, Wk, Wv);

    dim3 gMMA(NFLAT / 128, (BB * SS) / 128);
    qkv_mma_kernel<<<gMMA, 256, QKV_SMEM>>>(bq, bk, bv);

    dim3 gAtt(8, 64);
    attn_mma_kernel<<<gAtt, 256, ATT_SMEM>>>();

    headsum_kernel<<<(BB * SS * DHH) / 256, 256>>>();

    ff_kernel<<<(BB * SS) / 4, 256>>>(Wf, bf, out);
}

// round 5
// speedup vs baseline: 2.8987x; 1.4993x over previous
#include <cuda_runtime.h>
#include <cuda_bf16.h>
#include <math.h>
#include <stdint.h>

#define BB  4
#define SS  1024
#define DD  1024
#define HH  16
#define DHH 64
#define NFLAT 3072   // q:0-1023, k:1024-2047, v:2048-3071

// ---- persistent scratch (no allocations allowed) ----
__device__ float g_z[BB*HH*SS*DHH];     // per-head attention output
__device__ float g_sum[BB*SS*DHH];      // head-summed [t][e]

__device__ __nv_bfloat16 g_xhi[BB*SS*DD];
__device__ __nv_bfloat16 g_xlo[BB*SS*DD];
__device__ __nv_bfloat16 g_whi[NFLAT*DD];   // transposed: [n][k]
__device__ __nv_bfloat16 g_wlo[NFLAT*DD];

// attention operands, hi/lo split bf16, all [bh][s][e]
__device__ __nv_bfloat16 g_qhi[64*SS*DHH];
__device__ __nv_bfloat16 g_qlo[64*SS*DHH];
__device__ __nv_bfloat16 g_khi[64*SS*DHH];
__device__ __nv_bfloat16 g_klo[64*SS*DHH];
__device__ __nv_bfloat16 g_vhi[64*SS*DHH];
__device__ __nv_bfloat16 g_vlo[64*SS*DHH];

// ============================================================
// helpers
// ============================================================
__device__ __forceinline__ uint32_t smem_u32(const void* p) {
    uint32_t a;
    asm("{ .reg .u64 t; cvta.to.shared.u64 t, %1; cvt.u32.u64 %0, t; }"
        : "=r"(a) : "l"(p));
    return a;
}

#define CP16(dst, src) \
    asm volatile("cp.async.cg.shared.global [%0], [%1], 16;" \
                 :: "r"(dst), "l"(src) : "memory")
#define CP_COMMIT() asm volatile("cp.async.commit_group;" ::: "memory")
#define CP_WAIT1()  asm volatile("cp.async.wait_group 1;" ::: "memory")
#define CP_WAIT0()  asm volatile("cp.async.wait_group 0;" ::: "memory")

#define LDSM_X4(R, addr) \
    asm volatile("ldmatrix.sync.aligned.m8n8.x4.shared.b16 {%0,%1,%2,%3}, [%4];" \
                 : "=r"((R)[0]), "=r"((R)[1]), "=r"((R)[2]), "=r"((R)[3]) \
                 : "r"(addr))

#define LDSM_X4_T(R, addr) \
    asm volatile("ldmatrix.sync.aligned.m8n8.x4.trans.shared.b16 {%0,%1,%2,%3}, [%4];" \
                 : "=r"((R)[0]), "=r"((R)[1]), "=r"((R)[2]), "=r"((R)[3]) \
                 : "r"(addr))

#define MMA16816(D, A, B) \
    asm volatile("mma.sync.aligned.m16n8k16.row.col.f32.bf16.bf16.f32 " \
                 "{%0,%1,%2,%3}, {%4,%5,%6,%7}, {%8,%9}, {%0,%1,%2,%3};" \
                 : "+f"((D)[0]), "+f"((D)[1]), "+f"((D)[2]), "+f"((D)[3]) \
                 : "r"((A)[0]), "r"((A)[1]), "r"((A)[2]), "r"((A)[3]), \
                   "r"((B)[0]), "r"((B)[1]))

__device__ __forceinline__ uint32_t pack_bf16x2(float a, float b) {
    uint32_t r;
    asm("cvt.rn.bf16x2.f32 %0, %1, %2;" : "=r"(r) : "f"(b), "f"(a));
    return r;
}

// ============================================================
// Split x -> bf16 hi/lo
// ============================================================
__global__ __launch_bounds__(256) void split_x_kernel(const float* __restrict__ x)
{
    int i4 = blockIdx.x * 256 + threadIdx.x;
    float4 v = ((const float4*)x)[i4];
    __nv_bfloat16 h0 = __float2bfloat16(v.x);
    __nv_bfloat16 h1 = __float2bfloat16(v.y);
    __nv_bfloat16 h2 = __float2bfloat16(v.z);
    __nv_bfloat16 h3 = __float2bfloat16(v.w);
    __nv_bfloat16 l0 = __float2bfloat16(v.x - __bfloat162float(h0));
    __nv_bfloat16 l1 = __float2bfloat16(v.y - __bfloat162float(h1));
    __nv_bfloat16 l2 = __float2bfloat16(v.z - __bfloat162float(h2));
    __nv_bfloat16 l3 = __float2bfloat16(v.w - __bfloat162float(h3));
    __nv_bfloat162* ph = (__nv_bfloat162*)g_xhi;
    __nv_bfloat162* pl = (__nv_bfloat162*)g_xlo;
    ph[i4 * 2]     = __nv_bfloat162(h0, h1);
    ph[i4 * 2 + 1] = __nv_bfloat162(h2, h3);
    pl[i4 * 2]     = __nv_bfloat162(l0, l1);
    pl[i4 * 2 + 1] = __nv_bfloat162(l2, l3);
}

// ============================================================
// Split + transpose W -> g_whi/g_wlo [n=3072][k=1024]
// ============================================================
__global__ __launch_bounds__(256) void split_w_kernel(
    const float* __restrict__ Wq, const float* __restrict__ Wk,
    const float* __restrict__ Wv)
{
    __shared__ float ts[64][65];
    const int bid = blockIdx.x;
    const int hf = bid >> 4;
    const int kc = bid & 15;
    const int t = hf >> 4;
    const int h = hf & 15;
    const int k0 = kc * 64;
    const int tid = threadIdx.x;
    const float* W = (t == 0 ? Wq : (t == 1 ? Wk : Wv)) + (size_t)h * DD * DHH;

    #pragma unroll
    for (int j = 0; j < 16; j++) {
        int lin = j * 256 + tid;
        int kk = lin >> 6, e = lin & 63;
        ts[kk][e] = W[(size_t)(k0 + kk) * DHH + e];
    }
    __syncthreads();
    #pragma unroll
    for (int j = 0; j < 16; j++) {
        int lin = j * 256 + tid;
        int e = lin >> 6, kk = lin & 63;
        float v = ts[kk][e];
        __nv_bfloat16 hi = __float2bfloat16(v);
        __nv_bfloat16 lo = __float2bfloat16(v - __bfloat162float(hi));
        size_t o = ((size_t)(t * 1024 + h * 64 + e)) * DD + k0 + kk;
        g_whi[o] = hi;
        g_wlo[o] = lo;
    }
}

// ============================================================
// QKV projection via mma.sync bf16, 3x split.
// Epilogue writes bf16 hi/lo, uniform [bh][s][e] layout for Q, K and V.
// ============================================================
#define T_AH 0u
#define T_AL 8192u
#define T_BH 16384u
#define T_BL 24576u
#define STAGE_BYTES 32768u

__device__ __forceinline__ void qkv_load_stage(uint32_t sb, int stage,
                                               int m0, int n0, int k0)
{
    const int tid = threadIdx.x;
    const char* pAh = (const char*)g_xhi;
    const char* pAl = (const char*)g_xlo;
    const char* pBh = (const char*)g_whi;
    const char* pBl = (const char*)g_wlo;
    uint32_t base = sb + stage * STAGE_BYTES;
    #pragma unroll
    for (int i = 0; i < 2; i++) {
        int chunk = tid + i * 256;
        int r = chunk >> 2;
        int c = chunk & 3;
        uint32_t off = r * 64 + (((uint32_t)(c ^ ((r >> 1) & 3))) << 4);
        size_t ga = ((size_t)(m0 + r) * DD + k0) * 2 + c * 16;
        size_t gb = ((size_t)(n0 + r) * DD + k0) * 2 + c * 16;
        CP16(base + T_AH + off, pAh + ga);
        CP16(base + T_AL + off, pAl + ga);
        CP16(base + T_BH + off, pBh + gb);
        CP16(base + T_BL + off, pBl + gb);
    }
}

__global__ __launch_bounds__(256) void qkv_mma_kernel(
    const float* __restrict__ bq, const float* __restrict__ bk,
    const float* __restrict__ bv)
{
    extern __shared__ char dsm[];
    const uint32_t sb = smem_u32(dsm);

    const int tid = threadIdx.x;
    const int wid = tid >> 5;
    const int lane = tid & 31;
    const int warp_m = wid >> 2;
    const int warp_n = wid & 3;
    const int n0 = blockIdx.x * 128;
    const int m0 = blockIdx.y * 128;

    float acc[4][4][4];
    #pragma unroll
    for (int i = 0; i < 4; i++)
        #pragma unroll
        for (int j = 0; j < 4; j++)
            #pragma unroll
            for (int v = 0; v < 4; v++) acc[i][j][v] = 0.f;

    qkv_load_stage(sb, 0, m0, n0, 0);
    CP_COMMIT();

    for (int kb = 0; kb < 32; kb++) {
        if (kb < 31) {
            qkv_load_stage(sb, (kb + 1) & 1, m0, n0, (kb + 1) * 32);
            CP_COMMIT();
            CP_WAIT1();
        } else {
            CP_WAIT0();
        }
        __syncthreads();

        const uint32_t stg = sb + (kb & 1) * STAGE_BYTES;
        #pragma unroll
        for (int s = 0; s < 2; s++) {
            uint32_t ah[16], al[16];
            #pragma unroll
            for (int mt = 0; mt < 4; mt++) {
                int r = warp_m * 64 + mt * 16 + (lane & 15);
                int c = 2 * s + (lane >> 4);
                uint32_t off = r * 64 + (((uint32_t)(c ^ ((r >> 1) & 3))) << 4);
                LDSM_X4(&ah[mt * 4], stg + T_AH + off);
                LDSM_X4(&al[mt * 4], stg + T_AL + off);
            }
            uint32_t bh[8], bl[8];
            #pragma unroll
            for (int bt = 0; bt < 2; bt++) {
                int nr = warp_n * 32 + bt * 16 + ((lane >> 4) << 3) + (lane & 7);
                int c = 2 * s + ((lane >> 3) & 1);
                uint32_t off = nr * 64 + (((uint32_t)(c ^ ((nr >> 1) & 3))) << 4);
                LDSM_X4(&bh[bt * 4], stg + T_BH + off);
                LDSM_X4(&bl[bt * 4], stg + T_BL + off);
            }
            #pragma unroll
            for (int mt = 0; mt < 4; mt++)
                #pragma unroll
                for (int nt = 0; nt < 4; nt++) {
                    int bi = (nt >> 1) * 4 + (nt & 1) * 2;
                    MMA16816(acc[mt][nt], &ah[mt * 4], &bh[bi]);
                    MMA16816(acc[mt][nt], &ah[mt * 4], &bl[bi]);
                    MMA16816(acc[mt][nt], &al[mt * 4], &bh[bi]);
                }
        }
        __syncthreads();
    }

    // ---- epilogue: bias, hi/lo split, uniform scatter ----
    #pragma unroll
    for (int nt = 0; nt < 4; nt++) {
        int n = n0 + warp_n * 32 + nt * 8 + (lane & 3) * 2;
        int t = n >> 10;
        int h = (n >> 6) & 15;
        int e = n & 63;
        const float* bias = (t == 0 ? bq : (t == 1 ? bk : bv));
        __nv_bfloat16* dhi = (t == 0 ? g_qhi : (t == 1 ? g_khi : g_vhi));
        __nv_bfloat16* dlo = (t == 0 ? g_qlo : (t == 1 ? g_klo : g_vlo));
        float b0v = bias[h * 64 + e];
        float b1v = bias[h * 64 + e + 1];
        #pragma unroll
        for (int mt = 0; mt < 4; mt++) {
            #pragma unroll
            for (int half = 0; half < 2; half++) {
                int row = m0 + warp_m * 64 + mt * 16 + (lane >> 2) + half * 8;
                int b = row >> 10;
                int s = row & 1023;
                int bh = b * HH + h;
                float v0 = acc[mt][nt][half * 2]     + b0v;
                float v1 = acc[mt][nt][half * 2 + 1] + b1v;
                __nv_bfloat16 h0 = __float2bfloat16(v0);
                __nv_bfloat16 h1 = __float2bfloat16(v1);
                __nv_bfloat16 l0 = __float2bfloat16(v0 - __bfloat162float(h0));
                __nv_bfloat16 l1 = __float2bfloat16(v1 - __bfloat162float(h1));
                size_t o = ((size_t)(bh << 10) + s) * 64 + e;
                *(__nv_bfloat162*)&dhi[o] = __nv_bfloat162(h0, h1);
                *(__nv_bfloat162*)&dlo[o] = __nv_bfloat162(l0, l1);
            }
        }
    }
}

// ============================================================
// Flash attention via mma.sync, hi/lo split everywhere.
// V consumed from row-major [s][e] via ldmatrix.trans.
// ============================================================
#define AQ_H 0u
#define AQ_L 16384u
#define AST  32768u
#define AST_SZ 32768u
// within a stage: KH 0, KL 8192, VH 16384, VL 24576

__device__ __forceinline__ void attn_load_kv(uint32_t stg, int bh, int k0)
{
    const int tid = threadIdx.x;
    const char* kh = (const char*)g_khi;
    const char* kl = (const char*)g_klo;
    const char* vh = (const char*)g_vhi;
    const char* vl = (const char*)g_vlo;
    #pragma unroll
    for (int i = 0; i < 2; i++) {
        int ch = i * 256 + tid;        // 0..511
        int r = ch >> 3;               // 0..63
        int c = ch & 7;
        uint32_t off = r * 128 + (((uint32_t)(c ^ (r & 7))) << 4);
        size_t src = ((size_t)((bh << 10) + k0 + r)) * 128 + c * 16;
        CP16(stg + 0 + off, kh + src);
        CP16(stg + 8192 + off, kl + src);
        CP16(stg + 16384 + off, vh + src);
        CP16(stg + 24576 + off, vl + src);
    }
}

__global__ __launch_bounds__(256) void attn_mma_kernel()
{
    extern __shared__ char dsm[];
    const uint32_t sb = smem_u32(dsm);

    const int tid = threadIdx.x;
    const int wid = tid >> 5;
    const int lane = tid & 31;
    const int qt = 7 - blockIdx.x;     // heavy tiles first
    const int bh = blockIdx.y;
    const int q0 = qt * 128;
    const int n_kt = 2 * qt + 2;

    {
        const char* qh = (const char*)g_qhi;
        const char* ql = (const char*)g_qlo;
        #pragma unroll
        for (int i = 0; i < 4; i++) {
            int ch = i * 256 + tid;
            int r = ch >> 3;
            int c = ch & 7;
            uint32_t off = r * 128 + (((uint32_t)(c ^ (r & 7))) << 4);
            size_t src = ((size_t)((bh << 10) + q0 + r)) * 128 + c * 16;
            CP16(sb + AQ_H + off, qh + src);
            CP16(sb + AQ_L + off, ql + src);
        }
        attn_load_kv(sb + AST, bh, 0);
        CP_COMMIT();
    }

    float o[8][4];
    #pragma unroll
    for (int i = 0; i < 8; i++)
        #pragma unroll
        for (int j = 0; j < 4; j++) o[i][j] = 0.f;
    float m[2] = {-1e30f, -1e30f};
    float l[2] = {0.f, 0.f};
    uint32_t qfh[16], qfl[16];
    const int wr0 = q0 + wid * 16;

    for (int kt = 0; kt < n_kt; kt++) {
        if (kt + 1 < n_kt) {
            attn_load_kv(sb + AST + ((kt + 1) & 1) * AST_SZ, bh, (kt + 1) * 64);
            CP_COMMIT();
            CP_WAIT1();
        } else {
            CP_WAIT0();
        }
        __syncthreads();

        if (kt == 0) {
            #pragma unroll
            for (int ks = 0; ks < 4; ks++) {
                int r = wid * 16 + (lane & 15);
                int c = 2 * ks + (lane >> 4);
                uint32_t off = r * 128 + (((uint32_t)(c ^ (r & 7))) << 4);
                LDSM_X4(&qfh[ks * 4], sb + AQ_H + off);
                LDSM_X4(&qfl[ks * 4], sb + AQ_L + off);
            }
        }

        const int k0 = kt * 64;
        const bool skip = (k0 > wr0 + 15);
        if (!skip) {
            const uint32_t stg = sb + AST + (kt & 1) * AST_SZ;
            // ---- S = Q K^T ----
            float sc[8][4];
            #pragma unroll
            for (int i = 0; i < 8; i++)
                #pragma unroll
                for (int j = 0; j < 4; j++) sc[i][j] = 0.f;
            #pragma unroll
            for (int ks = 0; ks < 4; ks++) {
                uint32_t kfh[16], kfl[16];
                #pragma unroll
                for (int nt2 = 0; nt2 < 4; nt2++) {
                    int nr = nt2 * 16 + ((lane >> 4) << 3) + (lane & 7);
                    int c = 2 * ks + ((lane >> 3) & 1);
                    uint32_t off = nr * 128 + (((uint32_t)(c ^ (nr & 7))) << 4);
                    LDSM_X4(&kfh[nt2 * 4], stg + 0 + off);
                    LDSM_X4(&kfl[nt2 * 4], stg + 8192 + off);
                }
                #pragma unroll
                for (int nt = 0; nt < 8; nt++) {
                    int bi = (nt >> 1) * 4 + (nt & 1) * 2;
                    MMA16816(sc[nt], &qfh[ks * 4], &kfh[bi]);
                    MMA16816(sc[nt], &qfh[ks * 4], &kfl[bi]);
                    MMA16816(sc[nt], &qfl[ks * 4], &kfh[bi]);
                }
            }
            // ---- online softmax ----
            const bool need_mask = (k0 + 63 > wr0);
            uint32_t ph[16], pl[16];
            float alpha[2];
            #pragma unroll
            for (int rs = 0; rs < 2; rs++) {
                int grow = wr0 + (lane >> 2) + rs * 8;
                float mx = -1e30f;
                #pragma unroll
                for (int nt = 0; nt < 8; nt++) {
                    float v0 = sc[nt][rs * 2] * 0.125f;
                    float v1 = sc[nt][rs * 2 + 1] * 0.125f;
                    if (need_mask) {
                        int gc = k0 + nt * 8 + 2 * (lane & 3);
                        if (gc > grow) v0 = -1e30f;
                        if (gc + 1 > grow) v1 = -1e30f;
                    }
                    sc[nt][rs * 2] = v0;
                    sc[nt][rs * 2 + 1] = v1;
                    mx = fmaxf(mx, fmaxf(v0, v1));
                }
                mx = fmaxf(mx, __shfl_xor_sync(0xffffffffu, mx, 1));
                mx = fmaxf(mx, __shfl_xor_sync(0xffffffffu, mx, 2));
                float mn = fmaxf(m[rs], mx);
                alpha[rs] = __expf(m[rs] - mn);
                m[rs] = mn;
                float rsum = 0.f;
                #pragma unroll
                for (int nt = 0; nt < 8; nt++) {
                    float p0 = __expf(sc[nt][rs * 2] - mn);
                    float p1 = __expf(sc[nt][rs * 2 + 1] - mn);
                    rsum += p0 + p1;
                    uint32_t hp = pack_bf16x2(p0, p1);
                    float r0 = p0 - __uint_as_float(hp << 16);
                    float r1 = p1 - __uint_as_float(hp & 0xFFFF0000u);
                    uint32_t lp = pack_bf16x2(r0, r1);
                    int idx = (nt >> 1) * 4 + (nt & 1) * 2 + rs;
                    ph[idx] = hp;
                    pl[idx] = lp;
                }
                rsum += __shfl_xor_sync(0xffffffffu, rsum, 1);
                rsum += __shfl_xor_sync(0xffffffffu, rsum, 2);
                l[rs] = l[rs] * alpha[rs] + rsum;
                #pragma unroll
                for (int ne = 0; ne < 8; ne++) {
                    o[ne][rs * 2] *= alpha[rs];
                    o[ne][rs * 2 + 1] *= alpha[rs];
                }
            }
            // ---- O += P V  (V via trans-ldmatrix from row-major [s][e]) ----
            #pragma unroll
            for (int kp = 0; kp < 4; kp++) {
                uint32_t vfh[16], vfl[16];
                #pragma unroll
                for (int ne2 = 0; ne2 < 4; ne2++) {
                    int r = kp * 16 + (lane & 15);
                    int c = ne2 * 2 + (lane >> 4);
                    uint32_t off = r * 128 + (((uint32_t)(c ^ (r & 7))) << 4);
                    LDSM_X4_T(&vfh[ne2 * 4], stg + 16384 + off);
                    LDSM_X4_T(&vfl[ne2 * 4], stg + 24576 + off);
                }
                #pragma unroll
                for (int ne = 0; ne < 8; ne++) {
                    int bi = (ne >> 1) * 4 + (ne & 1) * 2;
                    MMA16816(o[ne], &ph[kp * 4], &vfh[bi]);
                    MMA16816(o[ne], &ph[kp * 4], &vfl[bi]);
                    MMA16816(o[ne], &pl[kp * 4], &vfh[bi]);
                }
            }
        }
        __syncthreads();
    }

    // ---- normalize + write ----
    #pragma unroll
    for (int rs = 0; rs < 2; rs++) {
        float inv = 1.f / l[rs];
        int row = (q0 + wid * 16) + (lane >> 2) + rs * 8;
        #pragma unroll
        for (int ne = 0; ne < 8; ne++) {
            int e = ne * 8 + 2 * (lane & 3);
            float2 r2;
            r2.x = o[ne][rs * 2] * inv;
            r2.y = o[ne][rs * 2 + 1] * inv;
            *(float2*)&g_z[((size_t)(bh << 10) + row) * 64 + e] = r2;
        }
    }
}

// ============================================================
__global__ __launch_bounds__(256) void headsum_kernel()
{
    int idx = blockIdx.x * blockDim.x + threadIdx.x;
    int e = idx & 63;
    int s = (idx >> 6) & 1023;
    int b = idx >> 16;
    const float* zp = g_z + ((size_t)(b * HH) * SS + s) * DHH + e;
    float acc = 0.f;
    #pragma unroll
    for (int h = 0; h < HH; h++) acc += zp[(size_t)h * SS * DHH];
    g_sum[idx] = acc;
}

// ============================================================
__device__ __forceinline__ float gelu_exact(float v)
{
    return 0.5f * v * (1.0f + erff(v * 0.70710678118654752f));
}

__global__ __launch_bounds__(256) void ff_kernel(const float* __restrict__ Wf,
                                                 const float* __restrict__ bf,
                                                 float* __restrict__ out)
{
    __shared__ float ssum[4][64];
    const int t0 = blockIdx.x * 4;
    const int tid = threadIdx.x;

    ssum[tid >> 6][tid & 63] = g_sum[(size_t)(t0 + (tid >> 6)) * DHH + (tid & 63)];
    __syncthreads();

    const int col = tid * 4;
    float acc[4][4];
    #pragma unroll
    for (int t = 0; t < 4; t++)
        #pragma unroll
        for (int j = 0; j < 4; j++) acc[t][j] = 0.f;

    #pragma unroll 8
    for (int e = 0; e < 64; e++) {
        float4 w = *(const float4*)&Wf[(size_t)e * DD + col];
        #pragma unroll
        for (int t = 0; t < 4; t++) {
            float sv = ssum[t][e];
            acc[t][0] += sv * w.x;
            acc[t][1] += sv * w.y;
            acc[t][2] += sv * w.z;
            acc[t][3] += sv * w.w;
        }
    }

    float4 b4 = *(const float4*)&bf[col];
    #pragma unroll
    for (int t = 0; t < 4; t++) {
        float4 r;
        r.x = gelu_exact(acc[t][0] + b4.x);
        r.y = gelu_exact(acc[t][1] + b4.y);
        r.z = gelu_exact(acc[t][2] + b4.z);
        r.w = gelu_exact(acc[t][3] + b4.w);
        *(float4*)&out[(size_t)(t0 + t) * DD + col] = r;
    }
}

// ============================================================
extern "C" void kernel_launch(void* const* d_in, const int* in_sizes, int n_in,
                              void* d_out, int out_size)
{
    const float* x  = (const float*)d_in[0];
    const float* Wq = (const float*)d_in[1];
    const float* bq = (const float*)d_in[2];
    const float* Wk = (const float*)d_in[3];
    const float* bk = (const float*)d_in[4];
    const float* Wv = (const float*)d_in[5];
    const float* bv = (const float*)d_in[6];
    const float* Wf = (const float*)d_in[7];
    const float* bf = (const float*)d_in[8];
    float* out = (float*)d_out;

    static const int QKV_SMEM = 65536;
    static const int ATT_SMEM = 98304;
    cudaFuncSetAttribute(qkv_mma_kernel,
                         cudaFuncAttributeMaxDynamicSharedMemorySize, QKV_SMEM);
    cudaFuncSetAttribute(attn_mma_kernel,
                         cudaFuncAttributeMaxDynamicSharedMemorySize, ATT_SMEM);

    split_x_kernel<<<(BB * SS * DD) / 4 / 256, 256>>>(x);
    split_w_kernel<<<48 * 16, 256>>>(Wq, Wk, Wv);

    dim3 gMMA(NFLAT / 128, (BB * SS) / 128);
    qkv_mma_kernel<<<gMMA, 256, QKV_SMEM>>>(bq, bk, bv);

    dim3 gAtt(8, 64);
    attn_mma_kernel<<<gAtt, 256, ATT_SMEM>>>();

    headsum_kernel<<<(BB * SS * DHH) / 256, 256>>>();

    ff_kernel<<<(BB * SS) / 4, 256>>>(Wf, bf, out);
}

// round 6
// speedup vs baseline: 2.9731x; 1.0257x over previous
#include <cuda_runtime.h>
#include <cuda_bf16.h>
#include <math.h>
#include <stdint.h>

#define BB  4
#define SS  1024
#define DD  1024
#define HH  16
#define DHH 64
#define NFLAT 3072   // q:0-1023, k:1024-2047, v:2048-3071

// ---- persistent scratch (no allocations allowed) ----
__device__ float g_z[BB*HH*SS*DHH];     // per-head attention output

__device__ __nv_bfloat16 g_xhi[BB*SS*DD];
__device__ __nv_bfloat16 g_xlo[BB*SS*DD];
__device__ __nv_bfloat16 g_whi[NFLAT*DD];   // transposed: [n][k]
__device__ __nv_bfloat16 g_wlo[NFLAT*DD];

// attention operands, hi/lo split bf16, all [bh][s][e]
__device__ __nv_bfloat16 g_qhi[64*SS*DHH];
__device__ __nv_bfloat16 g_qlo[64*SS*DHH];
__device__ __nv_bfloat16 g_khi[64*SS*DHH];
__device__ __nv_bfloat16 g_klo[64*SS*DHH];
__device__ __nv_bfloat16 g_vhi[64*SS*DHH];
__device__ __nv_bfloat16 g_vlo[64*SS*DHH];

// ============================================================
// helpers
// ============================================================
__device__ __forceinline__ uint32_t smem_u32(const void* p) {
    uint32_t a;
    asm("{ .reg .u64 t; cvta.to.shared.u64 t, %1; cvt.u32.u64 %0, t; }"
        : "=r"(a) : "l"(p));
    return a;
}

#define CP16(dst, src) \
    asm volatile("cp.async.cg.shared.global [%0], [%1], 16;" \
                 :: "r"(dst), "l"(src) : "memory")
#define CP_COMMIT() asm volatile("cp.async.commit_group;" ::: "memory")
#define CP_WAIT1()  asm volatile("cp.async.wait_group 1;" ::: "memory")
#define CP_WAIT0()  asm volatile("cp.async.wait_group 0;" ::: "memory")

#define LDSM_X4(R, addr) \
    asm volatile("ldmatrix.sync.aligned.m8n8.x4.shared.b16 {%0,%1,%2,%3}, [%4];" \
                 : "=r"((R)[0]), "=r"((R)[1]), "=r"((R)[2]), "=r"((R)[3]) \
                 : "r"(addr))

#define LDSM_X4_T(R, addr) \
    asm volatile("ldmatrix.sync.aligned.m8n8.x4.trans.shared.b16 {%0,%1,%2,%3}, [%4];" \
                 : "=r"((R)[0]), "=r"((R)[1]), "=r"((R)[2]), "=r"((R)[3]) \
                 : "r"(addr))

#define MMA16816(D, A, B) \
    asm volatile("mma.sync.aligned.m16n8k16.row.col.f32.bf16.bf16.f32 " \
                 "{%0,%1,%2,%3}, {%4,%5,%6,%7}, {%8,%9}, {%0,%1,%2,%3};" \
                 : "+f"((D)[0]), "+f"((D)[1]), "+f"((D)[2]), "+f"((D)[3]) \
                 : "r"((A)[0]), "r"((A)[1]), "r"((A)[2]), "r"((A)[3]), \
                   "r"((B)[0]), "r"((B)[1]))

__device__ __forceinline__ uint32_t pack_bf16x2(float a, float b) {
    uint32_t r;
    asm("cvt.rn.bf16x2.f32 %0, %1, %2;" : "=r"(r) : "f"(b), "f"(a));
    return r;
}

// ============================================================
// Split x -> bf16 hi/lo
// ============================================================
__global__ __launch_bounds__(256) void split_x_kernel(const float* __restrict__ x)
{
    int i4 = blockIdx.x * 256 + threadIdx.x;
    float4 v = ((const float4*)x)[i4];
    __nv_bfloat16 h0 = __float2bfloat16(v.x);
    __nv_bfloat16 h1 = __float2bfloat16(v.y);
    __nv_bfloat16 h2 = __float2bfloat16(v.z);
    __nv_bfloat16 h3 = __float2bfloat16(v.w);
    __nv_bfloat16 l0 = __float2bfloat16(v.x - __bfloat162float(h0));
    __nv_bfloat16 l1 = __float2bfloat16(v.y - __bfloat162float(h1));
    __nv_bfloat16 l2 = __float2bfloat16(v.z - __bfloat162float(h2));
    __nv_bfloat16 l3 = __float2bfloat16(v.w - __bfloat162float(h3));
    __nv_bfloat162* ph = (__nv_bfloat162*)g_xhi;
    __nv_bfloat162* pl = (__nv_bfloat162*)g_xlo;
    ph[i4 * 2]     = __nv_bfloat162(h0, h1);
    ph[i4 * 2 + 1] = __nv_bfloat162(h2, h3);
    pl[i4 * 2]     = __nv_bfloat162(l0, l1);
    pl[i4 * 2 + 1] = __nv_bfloat162(l2, l3);
}

// ============================================================
// Split + transpose W -> g_whi/g_wlo [n=3072][k=1024]
// ============================================================
__global__ __launch_bounds__(256) void split_w_kernel(
    const float* __restrict__ Wq, const float* __restrict__ Wk,
    const float* __restrict__ Wv)
{
    __shared__ float ts[64][65];
    const int bid = blockIdx.x;
    const int hf = bid >> 4;
    const int kc = bid & 15;
    const int t = hf >> 4;
    const int h = hf & 15;
    const int k0 = kc * 64;
    const int tid = threadIdx.x;
    const float* W = (t == 0 ? Wq : (t == 1 ? Wk : Wv)) + (size_t)h * DD * DHH;

    #pragma unroll
    for (int j = 0; j < 16; j++) {
        int lin = j * 256 + tid;
        int kk = lin >> 6, e = lin & 63;
        ts[kk][e] = W[(size_t)(k0 + kk) * DHH + e];
    }
    __syncthreads();
    #pragma unroll
    for (int j = 0; j < 16; j++) {
        int lin = j * 256 + tid;
        int e = lin >> 6, kk = lin & 63;
        float v = ts[kk][e];
        __nv_bfloat16 hi = __float2bfloat16(v);
        __nv_bfloat16 lo = __float2bfloat16(v - __bfloat162float(hi));
        size_t o = ((size_t)(t * 1024 + h * 64 + e)) * DD + k0 + kk;
        g_whi[o] = hi;
        g_wlo[o] = lo;
    }
}

// ============================================================
// QKV projection via mma.sync bf16, 3x split. BK=64, 2 stages.
// stage: Ah,Al,Bh,Bl each 128x64 bf16 (16KB) = 64KB; 128KB total.
// rows 128B wide, 8 chunks, swizzle c ^= r&7.
// ============================================================
#define T_AH 0u
#define T_AL 16384u
#define T_BH 32768u
#define T_BL 49152u
#define STAGE_BYTES 65536u

__device__ __forceinline__ void qkv_load_stage(uint32_t sb, int stage,
                                               int m0, int n0, int k0)
{
    const int tid = threadIdx.x;
    const char* pAh = (const char*)g_xhi;
    const char* pAl = (const char*)g_xlo;
    const char* pBh = (const char*)g_whi;
    const char* pBl = (const char*)g_wlo;
    uint32_t base = sb + stage * STAGE_BYTES;
    #pragma unroll
    for (int i = 0; i < 4; i++) {
        int chunk = tid + i * 256;            // 0..1023
        int r = chunk >> 3;
        int c = chunk & 7;
        uint32_t off = r * 128 + (((uint32_t)(c ^ (r & 7))) << 4);
        size_t ga = ((size_t)(m0 + r) * DD + k0) * 2 + c * 16;
        size_t gb = ((size_t)(n0 + r) * DD + k0) * 2 + c * 16;
        CP16(base + T_AH + off, pAh + ga);
        CP16(base + T_AL + off, pAl + ga);
        CP16(base + T_BH + off, pBh + gb);
        CP16(base + T_BL + off, pBl + gb);
    }
}

__global__ __launch_bounds__(256) void qkv_mma_kernel(
    const float* __restrict__ bq, const float* __restrict__ bk,
    const float* __restrict__ bv)
{
    extern __shared__ char dsm[];
    const uint32_t sb = smem_u32(dsm);

    const int tid = threadIdx.x;
    const int wid = tid >> 5;
    const int lane = tid & 31;
    const int warp_m = wid >> 2;
    const int warp_n = wid & 3;
    const int n0 = blockIdx.x * 128;
    const int m0 = blockIdx.y * 128;

    float acc[4][4][4];
    #pragma unroll
    for (int i = 0; i < 4; i++)
        #pragma unroll
        for (int j = 0; j < 4; j++)
            #pragma unroll
            for (int v = 0; v < 4; v++) acc[i][j][v] = 0.f;

    qkv_load_stage(sb, 0, m0, n0, 0);
    CP_COMMIT();

    for (int kb = 0; kb < 16; kb++) {
        if (kb < 15) {
            qkv_load_stage(sb, (kb + 1) & 1, m0, n0, (kb + 1) * 64);
            CP_COMMIT();
            CP_WAIT1();
        } else {
            CP_WAIT0();
        }
        __syncthreads();

        const uint32_t stg = sb + (kb & 1) * STAGE_BYTES;
        #pragma unroll
        for (int s = 0; s < 4; s++) {
            uint32_t ah[16], al[16];
            #pragma unroll
            for (int mt = 0; mt < 4; mt++) {
                int r = warp_m * 64 + mt * 16 + (lane & 15);
                int c = 2 * s + (lane >> 4);
                uint32_t off = r * 128 + (((uint32_t)(c ^ (r & 7))) << 4);
                LDSM_X4(&ah[mt * 4], stg + T_AH + off);
                LDSM_X4(&al[mt * 4], stg + T_AL + off);
            }
            uint32_t bh[8], bl[8];
            #pragma unroll
            for (int bt = 0; bt < 2; bt++) {
                int nr = warp_n * 32 + bt * 16 + ((lane >> 4) << 3) + (lane & 7);
                int c = 2 * s + ((lane >> 3) & 1);
                uint32_t off = nr * 128 + (((uint32_t)(c ^ (nr & 7))) << 4);
                LDSM_X4(&bh[bt * 4], stg + T_BH + off);
                LDSM_X4(&bl[bt * 4], stg + T_BL + off);
            }
            #pragma unroll
            for (int mt = 0; mt < 4; mt++)
                #pragma unroll
                for (int nt = 0; nt < 4; nt++) {
                    int bi = (nt >> 1) * 4 + (nt & 1) * 2;
                    MMA16816(acc[mt][nt], &ah[mt * 4], &bh[bi]);
                    MMA16816(acc[mt][nt], &ah[mt * 4], &bl[bi]);
                    MMA16816(acc[mt][nt], &al[mt * 4], &bh[bi]);
                }
        }
        __syncthreads();
    }

    // ---- epilogue: bias, hi/lo split, uniform scatter ----
    #pragma unroll
    for (int nt = 0; nt < 4; nt++) {
        int n = n0 + warp_n * 32 + nt * 8 + (lane & 3) * 2;
        int t = n >> 10;
        int h = (n >> 6) & 15;
        int e = n & 63;
        const float* bias = (t == 0 ? bq : (t == 1 ? bk : bv));
        __nv_bfloat16* dhi = (t == 0 ? g_qhi : (t == 1 ? g_khi : g_vhi));
        __nv_bfloat16* dlo = (t == 0 ? g_qlo : (t == 1 ? g_klo : g_vlo));
        float b0v = bias[h * 64 + e];
        float b1v = bias[h * 64 + e + 1];
        #pragma unroll
        for (int mt = 0; mt < 4; mt++) {
            #pragma unroll
            for (int half = 0; half < 2; half++) {
                int row = m0 + warp_m * 64 + mt * 16 + (lane >> 2) + half * 8;
                int b = row >> 10;
                int s = row & 1023;
                int bh = b * HH + h;
                float v0 = acc[mt][nt][half * 2]     + b0v;
                float v1 = acc[mt][nt][half * 2 + 1] + b1v;
                __nv_bfloat16 h0 = __float2bfloat16(v0);
                __nv_bfloat16 h1 = __float2bfloat16(v1);
                __nv_bfloat16 l0 = __float2bfloat16(v0 - __bfloat162float(h0));
                __nv_bfloat16 l1 = __float2bfloat16(v1 - __bfloat162float(h1));
                size_t o = ((size_t)(bh << 10) + s) * 64 + e;
                *(__nv_bfloat162*)&dhi[o] = __nv_bfloat162(h0, h1);
                *(__nv_bfloat162*)&dlo[o] = __nv_bfloat162(l0, l1);
            }
        }
    }
}

// ============================================================
// Flash attention via mma.sync, hi/lo split, K-tile = 128.
// smem: stages at 0 (2 x 64KB: KH 0, KL 16K, VH 32K, VL 48K), Q at 128KB.
// ============================================================
#define AST    0u
#define AST_SZ 65536u
#define AQ_H   131072u
#define AQ_L   147456u

__device__ __forceinline__ void attn_load_kv(uint32_t stg, int bh, int k0)
{
    const int tid = threadIdx.x;
    const char* kh = (const char*)g_khi;
    const char* kl = (const char*)g_klo;
    const char* vh = (const char*)g_vhi;
    const char* vl = (const char*)g_vlo;
    #pragma unroll
    for (int i = 0; i < 4; i++) {
        int ch = i * 256 + tid;        // 0..1023
        int r = ch >> 3;               // 0..127
        int c = ch & 7;
        uint32_t off = r * 128 + (((uint32_t)(c ^ (r & 7))) << 4);
        size_t src = ((size_t)((bh << 10) + k0 + r)) * 128 + c * 16;
        CP16(stg + 0 + off, kh + src);
        CP16(stg + 16384 + off, kl + src);
        CP16(stg + 32768 + off, vh + src);
        CP16(stg + 49152 + off, vl + src);
    }
}

__global__ __launch_bounds__(256) void attn_mma_kernel()
{
    extern __shared__ char dsm[];
    const uint32_t sb = smem_u32(dsm);

    const int tid = threadIdx.x;
    const int wid = tid >> 5;
    const int lane = tid & 31;
    const int qt = 7 - blockIdx.x;     // heavy tiles first
    const int bh = blockIdx.y;
    const int q0 = qt * 128;
    const int n_kt = qt + 1;           // 128-wide K tiles

    {
        const char* qh = (const char*)g_qhi;
        const char* ql = (const char*)g_qlo;
        #pragma unroll
        for (int i = 0; i < 4; i++) {
            int ch = i * 256 + tid;
            int r = ch >> 3;
            int c = ch & 7;
            uint32_t off = r * 128 + (((uint32_t)(c ^ (r & 7))) << 4);
            size_t src = ((size_t)((bh << 10) + q0 + r)) * 128 + c * 16;
            CP16(sb + AQ_H + off, qh + src);
            CP16(sb + AQ_L + off, ql + src);
        }
        attn_load_kv(sb + AST, bh, 0);
        CP_COMMIT();
    }

    float o[8][4];
    #pragma unroll
    for (int i = 0; i < 8; i++)
        #pragma unroll
        for (int j = 0; j < 4; j++) o[i][j] = 0.f;
    float m[2] = {-1e30f, -1e30f};
    float l[2] = {0.f, 0.f};
    uint32_t qfh[16], qfl[16];
    const int wr0 = q0 + wid * 16;

    for (int kt = 0; kt < n_kt; kt++) {
        if (kt + 1 < n_kt) {
            attn_load_kv(sb + AST + ((kt + 1) & 1) * AST_SZ, bh, (kt + 1) * 128);
            CP_COMMIT();
            CP_WAIT1();
        } else {
            CP_WAIT0();
        }
        __syncthreads();

        if (kt == 0) {
            #pragma unroll
            for (int ks = 0; ks < 4; ks++) {
                int r = wid * 16 + (lane & 15);
                int c = 2 * ks + (lane >> 4);
                uint32_t off = r * 128 + (((uint32_t)(c ^ (r & 7))) << 4);
                LDSM_X4(&qfh[ks * 4], sb + AQ_H + off);
                LDSM_X4(&qfl[ks * 4], sb + AQ_L + off);
            }
        }

        const int k0 = kt * 128;
        const uint32_t stg = sb + AST + (kt & 1) * AST_SZ;
        // ---- S = Q K^T  (16 rows x 128 cols per warp) ----
        float sc[16][4];
        #pragma unroll
        for (int i = 0; i < 16; i++)
            #pragma unroll
            for (int j = 0; j < 4; j++) sc[i][j] = 0.f;
        #pragma unroll
        for (int ks = 0; ks < 4; ks++) {
            uint32_t kfh[32], kfl[32];
            #pragma unroll
            for (int nt2 = 0; nt2 < 8; nt2++) {
                int nr = nt2 * 16 + ((lane >> 4) << 3) + (lane & 7);
                int c = 2 * ks + ((lane >> 3) & 1);
                uint32_t off = nr * 128 + (((uint32_t)(c ^ (nr & 7))) << 4);
                LDSM_X4(&kfh[nt2 * 4], stg + 0 + off);
                LDSM_X4(&kfl[nt2 * 4], stg + 16384 + off);
            }
            #pragma unroll
            for (int nt = 0; nt < 16; nt++) {
                int bi = (nt >> 1) * 4 + (nt & 1) * 2;
                MMA16816(sc[nt], &qfh[ks * 4], &kfh[bi]);
                MMA16816(sc[nt], &qfh[ks * 4], &kfl[bi]);
                MMA16816(sc[nt], &qfl[ks * 4], &kfh[bi]);
            }
        }
        // ---- online softmax over 128 cols ----
        const bool need_mask = (k0 + 127 > wr0);
        uint32_t ph[32], pl[32];
        float alpha[2];
        #pragma unroll
        for (int rs = 0; rs < 2; rs++) {
            int grow = wr0 + (lane >> 2) + rs * 8;
            float mx = -1e30f;
            #pragma unroll
            for (int nt = 0; nt < 16; nt++) {
                float v0 = sc[nt][rs * 2] * 0.125f;
                float v1 = sc[nt][rs * 2 + 1] * 0.125f;
                if (need_mask) {
                    int gc = k0 + nt * 8 + 2 * (lane & 3);
                    if (gc > grow) v0 = -1e30f;
                    if (gc + 1 > grow) v1 = -1e30f;
                }
                sc[nt][rs * 2] = v0;
                sc[nt][rs * 2 + 1] = v1;
                mx = fmaxf(mx, fmaxf(v0, v1));
            }
            mx = fmaxf(mx, __shfl_xor_sync(0xffffffffu, mx, 1));
            mx = fmaxf(mx, __shfl_xor_sync(0xffffffffu, mx, 2));
            float mn = fmaxf(m[rs], mx);
            alpha[rs] = __expf(m[rs] - mn);
            m[rs] = mn;
            float rsum = 0.f;
            #pragma unroll
            for (int nt = 0; nt < 16; nt++) {
                float p0 = __expf(sc[nt][rs * 2] - mn);
                float p1 = __expf(sc[nt][rs * 2 + 1] - mn);
                rsum += p0 + p1;
                uint32_t hp = pack_bf16x2(p0, p1);
                float r0 = p0 - __uint_as_float(hp << 16);
                float r1 = p1 - __uint_as_float(hp & 0xFFFF0000u);
                uint32_t lp = pack_bf16x2(r0, r1);
                int idx = (nt >> 1) * 4 + (nt & 1) * 2 + rs;
                ph[idx] = hp;
                pl[idx] = lp;
            }
            rsum += __shfl_xor_sync(0xffffffffu, rsum, 1);
            rsum += __shfl_xor_sync(0xffffffffu, rsum, 2);
            l[rs] = l[rs] * alpha[rs] + rsum;
            #pragma unroll
            for (int ne = 0; ne < 8; ne++) {
                o[ne][rs * 2] *= alpha[rs];
                o[ne][rs * 2 + 1] *= alpha[rs];
            }
        }
        // ---- O += P V  (V via trans-ldmatrix from row-major [s][e]) ----
        #pragma unroll
        for (int kp = 0; kp < 8; kp++) {
            uint32_t vfh[16], vfl[16];
            #pragma unroll
            for (int ne2 = 0; ne2 < 4; ne2++) {
                int r = kp * 16 + (lane & 15);
                int c = ne2 * 2 + (lane >> 4);
                uint32_t off = r * 128 + (((uint32_t)(c ^ (r & 7))) << 4);
                LDSM_X4_T(&vfh[ne2 * 4], stg + 32768 + off);
                LDSM_X4_T(&vfl[ne2 * 4], stg + 49152 + off);
            }
            #pragma unroll
            for (int ne = 0; ne < 8; ne++) {
                int bi = (ne >> 1) * 4 + (ne & 1) * 2;
                MMA16816(o[ne], &ph[kp * 4], &vfh[bi]);
                MMA16816(o[ne], &ph[kp * 4], &vfl[bi]);
                MMA16816(o[ne], &pl[kp * 4], &vfh[bi]);
            }
        }
        __syncthreads();
    }

    // ---- normalize + write ----
    #pragma unroll
    for (int rs = 0; rs < 2; rs++) {
        float inv = 1.f / l[rs];
        int row = (q0 + wid * 16) + (lane >> 2) + rs * 8;
        #pragma unroll
        for (int ne = 0; ne < 8; ne++) {
            int e = ne * 8 + 2 * (lane & 3);
            float2 r2;
            r2.x = o[ne][rs * 2] * inv;
            r2.y = o[ne][rs * 2 + 1] * inv;
            *(float2*)&g_z[((size_t)(bh << 10) + row) * 64 + e] = r2;
        }
    }
}

// ============================================================
// FF with fused head-sum: out = gelu((sum_h z) @ Wf + bf)
// ============================================================
__device__ __forceinline__ float gelu_exact(float v)
{
    return 0.5f * v * (1.0f + erff(v * 0.70710678118654752f));
}

__global__ __launch_bounds__(256) void ff_kernel(const float* __restrict__ Wf,
                                                 const float* __restrict__ bf,
                                                 float* __restrict__ out)
{
    __shared__ float ssum[4][64];
    const int t0 = blockIdx.x * 4;
    const int tid = threadIdx.x;

    // fused head sum: thread -> (token, e)
    {
        int t = tid >> 6;
        int e = tid & 63;
        int tok = t0 + t;
        int b = tok >> 10;
        int s = tok & 1023;
        const float* zp = g_z + ((size_t)(b * HH) * SS + s) * DHH + e;
        float acc = 0.f;
        #pragma unroll
        for (int h = 0; h < HH; h++) acc += zp[(size_t)h * SS * DHH];
        ssum[t][e] = acc;
    }
    __syncthreads();

    const int col = tid * 4;
    float acc[4][4];
    #pragma unroll
    for (int t = 0; t < 4; t++)
        #pragma unroll
        for (int j = 0; j < 4; j++) acc[t][j] = 0.f;

    #pragma unroll 8
    for (int e = 0; e < 64; e++) {
        float4 w = *(const float4*)&Wf[(size_t)e * DD + col];
        #pragma unroll
        for (int t = 0; t < 4; t++) {
            float sv = ssum[t][e];
            acc[t][0] += sv * w.x;
            acc[t][1] += sv * w.y;
            acc[t][2] += sv * w.z;
            acc[t][3] += sv * w.w;
        }
    }

    float4 b4 = *(const float4*)&bf[col];
    #pragma unroll
    for (int t = 0; t < 4; t++) {
        float4 r;
        r.x = gelu_exact(acc[t][0] + b4.x);
        r.y = gelu_exact(acc[t][1] + b4.y);
        r.z = gelu_exact(acc[t][2] + b4.z);
        r.w = gelu_exact(acc[t][3] + b4.w);
        *(float4*)&out[(size_t)(t0 + t) * DD + col] = r;
    }
}

// ============================================================
extern "C" void kernel_launch(void* const* d_in, const int* in_sizes, int n_in,
                              void* d_out, int out_size)
{
    const float* x  = (const float*)d_in[0];
    const float* Wq = (const float*)d_in[1];
    const float* bq = (const float*)d_in[2];
    const float* Wk = (const float*)d_in[3];
    const float* bk = (const float*)d_in[4];
    const float* Wv = (const float*)d_in[5];
    const float* bv = (const float*)d_in[6];
    const float* Wf = (const float*)d_in[7];
    const float* bf = (const float*)d_in[8];
    float* out = (float*)d_out;

    static const int QKV_SMEM = 131072;   // 2 stages x 64KB
    static const int ATT_SMEM = 163840;   // 2 stages x 64KB + Q 32KB
    cudaFuncSetAttribute(qkv_mma_kernel,
                         cudaFuncAttributeMaxDynamicSharedMemorySize, QKV_SMEM);
    cudaFuncSetAttribute(attn_mma_kernel,
                         cudaFuncAttributeMaxDynamicSharedMemorySize, ATT_SMEM);

    split_x_kernel<<<(BB * SS * DD) / 4 / 256, 256>>>(x);
    split_w_kernel<<<48 * 16, 256>>>(Wq, Wk, Wv);

    dim3 gMMA(NFLAT / 128, (BB * SS) / 128);
    qkv_mma_kernel<<<gMMA, 256, QKV_SMEM>>>(bq, bk, bv);

    dim3 gAtt(8, 64);
    attn_mma_kernel<<<gAtt, 256, ATT_SMEM>>>();

    ff_kernel<<<(BB * SS) / 4, 256>>>(Wf, bf, out);
}